// round 1
// baseline (speedup 1.0000x reference)
#include <cuda_runtime.h>
#include <math.h>

#define CDIV(a,b) (((a)+(b)-1)/(b))

constexpr int NI     = 8;
constexpr int FSZ    = 20;
constexpr int NANCH  = 10000;
constexpr int SORTN  = 16384;
constexpr int PRENMS = 1000;
constexpr int NROIS  = 200;

// ---- scratch layout (floats) ----
constexpr size_t O_C1  = 0;                constexpr size_t S_C1  = (size_t)NI*24*160*160;
constexpr size_t O_P1  = O_C1 + S_C1;      constexpr size_t S_P1  = (size_t)NI*24*80*80;
constexpr size_t O_C3  = O_P1 + S_P1;      constexpr size_t S_C3  = (size_t)NI*132*40*40;
constexpr size_t O_C4  = O_C3 + S_C3;      constexpr size_t S_C4  = (size_t)NI*264*20*20;
constexpr size_t O_C5  = O_C4 + S_C4;      constexpr size_t S_C5  = (size_t)NI*528*10*10;
constexpr size_t O_GLB = O_C5 + S_C5;      constexpr size_t S_GLB = (size_t)NI*528;
constexpr size_t O_GFC = O_GLB + S_GLB;    constexpr size_t S_GFC = (size_t)NI*245;
constexpr size_t O_CEM5= O_GFC + S_GFC;    constexpr size_t S_CEM5= (size_t)NI*245*100;
constexpr size_t O_FCEM= O_CEM5 + S_CEM5;  constexpr size_t S_FCEM= (size_t)NI*245*400;
constexpr size_t O_T   = O_FCEM + S_FCEM;  constexpr size_t S_T   = S_FCEM;
constexpr size_t O_FRPN= O_T + S_T;        constexpr size_t S_FRPN= (size_t)NI*256*400;
constexpr size_t O_CLS = O_FRPN + S_FRPN;  constexpr size_t S_CLS = (size_t)NI*50*400;
constexpr size_t O_REG = O_CLS + S_CLS;    constexpr size_t S_REG = (size_t)NI*100*400;
constexpr size_t O_FSAM= O_REG + S_REG;    constexpr size_t S_FSAM= S_FCEM;
constexpr size_t O_BOX = O_FSAM + S_FSAM;  constexpr size_t S_BOX = (size_t)NI*NANCH*4;
constexpr size_t O_BK  = O_BOX + S_BOX;    constexpr size_t S_BK  = (size_t)NI*PRENMS*4;
constexpr size_t O_ROI = O_BK + S_BK;      constexpr size_t S_ROI = (size_t)NI*NROIS*4;
constexpr size_t O_FROI= O_ROI + S_ROI;    constexpr size_t S_FROI= (size_t)NI*NROIS*245;
constexpr size_t O_H   = O_FROI + S_FROI;  constexpr size_t S_H   = (size_t)NI*NROIS*1024;
constexpr size_t TOTAL = O_H + S_H;

__device__ float g_buf[TOTAL];
__device__ unsigned long long g_keys[(size_t)NI*SORTN];

// ---- 3x3 stride-2 conv + relu, SAME padding (pad_lo=0, pad_hi=1 for even inputs) ----
__global__ void conv3x3s2_relu(const float* __restrict__ in, const float* __restrict__ w,
                               const float* __restrict__ bias, float* __restrict__ out,
                               int Cin, int Hin, int Cout, int Hout) {
    int t = blockIdx.x*blockDim.x + threadIdx.x;
    int total = NI*Cout*Hout*Hout;
    if (t >= total) return;
    int ox = t % Hout;
    int oy = (t / Hout) % Hout;
    int oc = (t / (Hout*Hout)) % Cout;
    int n  = t / (Hout*Hout*Cout);
    float s = bias[oc];
    const float* wp = w + (size_t)oc*Cin*9;
    const float* ip = in + (size_t)n*Cin*Hin*Hin;
    int iy0 = 2*oy, ix0 = 2*ox;
    for (int ic = 0; ic < Cin; ic++) {
        const float* irow = ip + (size_t)ic*Hin*Hin;
        const float* wk = wp + ic*9;
        #pragma unroll
        for (int ky = 0; ky < 3; ky++) {
            int iy = iy0 + ky;
            if (iy >= Hin) continue;
            #pragma unroll
            for (int kx = 0; kx < 3; kx++) {
                int ix = ix0 + kx;
                if (ix >= Hin) continue;
                s += irow[iy*Hin+ix] * wk[ky*3+kx];
            }
        }
    }
    out[t] = fmaxf(s, 0.f);
}

// ---- 3x3 stride-2 maxpool SAME ----
__global__ void maxpool3s2(const float* __restrict__ in, float* __restrict__ out,
                           int C, int Hin, int Hout) {
    int t = blockIdx.x*blockDim.x + threadIdx.x;
    int total = NI*C*Hout*Hout;
    if (t >= total) return;
    int ox = t % Hout;
    int oy = (t / Hout) % Hout;
    int nc = t / (Hout*Hout);
    const float* ip = in + (size_t)nc*Hin*Hin;
    float m = -INFINITY;
    #pragma unroll
    for (int ky = 0; ky < 3; ky++) {
        int iy = 2*oy + ky;
        if (iy >= Hin) continue;
        #pragma unroll
        for (int kx = 0; kx < 3; kx++) {
            int ix = 2*ox + kx;
            if (ix >= Hin) continue;
            m = fmaxf(m, ip[iy*Hin+ix]);
        }
    }
    out[t] = m;
}

// ---- global average pool of c5: (NI,528,10,10) -> (NI,528) ----
__global__ void gap_kernel(const float* __restrict__ c5, float* __restrict__ glb) {
    int t = blockIdx.x*blockDim.x + threadIdx.x;
    if (t >= NI*528) return;
    const float* p = c5 + (size_t)t*100;
    float s = 0.f;
    for (int i = 0; i < 100; i++) s += p[i];
    glb[t] = s / 100.f;
}

// ---- gfc[n,k] = glb[n,:] @ wg[:,k] + bg[k] ----
__global__ void gfc_kernel(const float* __restrict__ glb, const float* __restrict__ wg,
                           const float* __restrict__ bg, float* __restrict__ gfc) {
    int t = blockIdx.x*blockDim.x + threadIdx.x;
    if (t >= NI*245) return;
    int k = t % 245, n = t / 245;
    float s = bg[k];
    const float* g = glb + n*528;
    for (int c = 0; c < 528; c++) s += g[c] * wg[c*245 + k];
    gfc[t] = s;
}

// ---- generic 1x1 conv ----
__global__ void conv1x1(const float* __restrict__ in, const float* __restrict__ w,
                        const float* __restrict__ bias, float* __restrict__ out,
                        int Cin, int Cout, int P, int doRelu) {
    int t = blockIdx.x*blockDim.x + threadIdx.x;
    int total = NI*Cout*P;
    if (t >= total) return;
    int p  = t % P;
    int oc = (t / P) % Cout;
    int n  = t / (P*Cout);
    const float* ip = in + (size_t)n*Cin*P + p;
    const float* wp = w + (size_t)oc*Cin;
    float s = bias[oc];
    for (int ic = 0; ic < Cin; ic++) s += ip[(size_t)ic*P] * wp[ic];
    out[t] = doRelu ? fmaxf(s, 0.f) : s;
}

// ---- fcem = 1x1(c4) + up2(cem5) + gfc broadcast ----
__global__ void fcem_kernel(const float* __restrict__ c4, const float* __restrict__ w4c,
                            const float* __restrict__ b4c, const float* __restrict__ gfc,
                            const float* __restrict__ cem5, float* __restrict__ fcem) {
    int t = blockIdx.x*blockDim.x + threadIdx.x;
    int total = NI*245*400;
    if (t >= total) return;
    int p = t % 400;
    int k = (t / 400) % 245;
    int n = t / (400*245);
    int y = p / 20, x = p % 20;
    float s = b4c[k] + gfc[n*245 + k] + cem5[((size_t)n*245 + k)*100 + (y/2)*10 + (x/2)];
    const float* ip = c4 + (size_t)n*264*400 + p;
    const float* wp = w4c + (size_t)k*264;
    for (int ic = 0; ic < 264; ic++) s += ip[(size_t)ic*400] * wp[ic];
    fcem[t] = s;
}

// ---- depthwise 5x5 SAME + relu ----
__global__ void dw5_kernel(const float* __restrict__ in, const float* __restrict__ w,
                           const float* __restrict__ bias, float* __restrict__ out) {
    int t = blockIdx.x*blockDim.x + threadIdx.x;
    int total = NI*245*400;
    if (t >= total) return;
    int p = t % 400;
    int k = (t / 400) % 245;
    int y = p / 20, x = p % 20;
    const float* ip = in + (size_t)(t/400)*400;
    const float* wk = w + k*25;
    float s = bias[k];
    #pragma unroll
    for (int ky = 0; ky < 5; ky++) {
        int iy = y - 2 + ky;
        if (iy < 0 || iy >= 20) continue;
        #pragma unroll
        for (int kx = 0; kx < 5; kx++) {
            int ix = x - 2 + kx;
            if (ix < 0 || ix >= 20) continue;
            s += ip[iy*20+ix] * wk[ky*5+kx];
        }
    }
    out[t] = fmaxf(s, 0.f);
}

// ---- fsam = fcem * sigmoid(1x1(frpn, sam_w)) ----
__global__ void fsam_kernel(const float* __restrict__ frpn, const float* __restrict__ samw,
                            const float* __restrict__ samb, const float* __restrict__ fcem,
                            float* __restrict__ fsam) {
    int t = blockIdx.x*blockDim.x + threadIdx.x;
    int total = NI*245*400;
    if (t >= total) return;
    int p = t % 400;
    int k = (t / 400) % 245;
    int n = t / (400*245);
    const float* ip = frpn + (size_t)n*256*400 + p;
    const float* wp = samw + (size_t)k*256;
    float s = samb[k];
    for (int ic = 0; ic < 256; ic++) s += ip[(size_t)ic*400] * wp[ic];
    fsam[t] = fcem[t] * (1.f / (1.f + expf(-s)));
}

// ---- scores + decoded boxes + sort keys ----
__global__ void scorebox_kernel(const float* __restrict__ clsmap, const float* __restrict__ regmap,
                                float* __restrict__ boxes, unsigned long long* __restrict__ keys) {
    int t = blockIdx.x*blockDim.x + threadIdx.x;
    if (t >= NI*SORTN) return;
    int i = t % SORTN;
    int n = t / SORTN;
    if (i >= NANCH) { keys[t] = 0ull; return; }
    int a = i % 25;
    int x = (i / 25) % 20;
    int y = i / 500;
    int p = y*20 + x;
    const float* cm = clsmap + (size_t)n*50*400;
    float c0 = cm[(a*2  )*400 + p];
    float c1 = cm[(a*2+1)*400 + p];
    float score = 1.f / (1.f + expf(c0 - c1));
    const float* rm = regmap + (size_t)n*100*400;
    float d0 = rm[(a*4  )*400 + p];
    float d1 = rm[(a*4+1)*400 + p];
    float d2 = rm[(a*4+2)*400 + p];
    float d3 = rm[(a*4+3)*400 + p];
    const float scales[5] = {32.f, 64.f, 128.f, 256.f, 512.f};
    const float ratios[5] = {0.5f, 0.75f, 1.0f, 4.0f/3.0f, 2.0f};
    int si = a / 5, ri = a % 5;
    float sq = sqrtf(ratios[ri]);
    float aw = scales[si] / sq;
    float ah = scales[si] * sq;
    float acx = (x + 0.5f) * 16.f;
    float acy = (y + 0.5f) * 16.f;
    float cx = d0*aw + acx;
    float cy = d1*ah + acy;
    float w  = expf(d2) * aw;
    float h  = expf(d3) * ah;
    float* b = boxes + ((size_t)n*NANCH + i)*4;
    b[0] = fminf(fmaxf(cx - 0.5f*w, 0.f), 319.f);
    b[1] = fminf(fmaxf(cy - 0.5f*h, 0.f), 319.f);
    b[2] = fminf(fmaxf(cx + 0.5f*w, 0.f), 319.f);
    b[3] = fminf(fmaxf(cy + 0.5f*h, 0.f), 319.f);
    unsigned sb = __float_as_uint(score);  // score >= 0 -> bit-monotone
    keys[t] = ((unsigned long long)sb << 32) | (unsigned long long)(0xFFFFFFFFu - (unsigned)i);
}

// ---- per-image bitonic sort (descending) over 16384 keys; then gather top-1000 boxes ----
__global__ void sort_kernel(unsigned long long* __restrict__ keys,
                            const float* __restrict__ boxes, float* __restrict__ bk) {
    extern __shared__ unsigned long long sk[];
    int n = blockIdx.x;
    unsigned long long* g = keys + (size_t)n*SORTN;
    for (int i = threadIdx.x; i < SORTN; i += blockDim.x) sk[i] = g[i];
    __syncthreads();
    for (int size = 2; size <= SORTN; size <<= 1) {
        for (int stride = size >> 1; stride > 0; stride >>= 1) {
            for (int t = threadIdx.x; t < SORTN/2; t += blockDim.x) {
                int lo = ((t & ~(stride-1)) << 1) | (t & (stride-1));
                int hi = lo + stride;
                unsigned long long a = sk[lo], c = sk[hi];
                bool desc = ((lo & size) == 0);
                bool sw = desc ? (a < c) : (a > c);
                if (sw) { sk[lo] = c; sk[hi] = a; }
            }
            __syncthreads();
        }
    }
    for (int j = threadIdx.x; j < PRENMS; j += blockDim.x) {
        unsigned idx = 0xFFFFFFFFu - (unsigned)(sk[j] & 0xFFFFFFFFull);
        const float* src = boxes + ((size_t)n*NANCH + idx)*4;
        float* dst = bk + ((size_t)n*PRENMS + j)*4;
        dst[0] = src[0]; dst[1] = src[1]; dst[2] = src[2]; dst[3] = src[3];
    }
}

// ---- sequential NMS + stable partition -> 200 rois (also writes rois output section) ----
__global__ void nms_kernel(const float* __restrict__ bk, float* __restrict__ rois,
                           float* __restrict__ out_rois) {
    __shared__ float4 box[PRENMS];
    __shared__ float  area[PRENMS];
    __shared__ int    supp[PRENMS];
    __shared__ int    order[NROIS];
    int n = blockIdx.x;
    const float* b = bk + (size_t)n*PRENMS*4;
    for (int i = threadIdx.x; i < PRENMS; i += blockDim.x) {
        float x1 = b[i*4], y1 = b[i*4+1], x2 = b[i*4+2], y2 = b[i*4+3];
        box[i] = make_float4(x1, y1, x2, y2);
        area[i] = (x2-x1)*(y2-y1);
        supp[i] = 0;
    }
    __syncthreads();
    for (int i = 0; i < PRENMS; i++) {
        if (!supp[i]) {
            float4 bi = box[i];
            float ai = area[i];
            for (int j = i + 1 + threadIdx.x; j < PRENMS; j += blockDim.x) {
                float ix1 = fmaxf(bi.x, box[j].x);
                float iy1 = fmaxf(bi.y, box[j].y);
                float ix2 = fminf(bi.z, box[j].z);
                float iy2 = fminf(bi.w, box[j].w);
                float inter = fmaxf(ix2-ix1, 0.f) * fmaxf(iy2-iy1, 0.f);
                float iou = inter / (ai + area[j] - inter + 1e-9f);
                if (iou > 0.7f) supp[j] = 1;
            }
        }
        __syncthreads();
    }
    if (threadIdx.x == 0) {
        int c = 0;
        for (int i = 0; i < PRENMS && c < NROIS; i++) if (!supp[i]) order[c++] = i;
        for (int i = 0; i < PRENMS && c < NROIS; i++) if ( supp[i]) order[c++] = i;
    }
    __syncthreads();
    for (int r = threadIdx.x; r < NROIS; r += blockDim.x) {
        float4 bb = box[order[r]];
        float* dst = rois + ((size_t)n*NROIS + r)*4;
        dst[0] = bb.x; dst[1] = bb.y; dst[2] = bb.z; dst[3] = bb.w;
        float* o = out_rois + ((size_t)n*NROIS + r)*4;
        o[0] = bb.x; o[1] = bb.y; o[2] = bb.z; o[3] = bb.w;
    }
}

// ---- PSRoI pooling: froi[n*200 + r][c] with c = a*49 + i*7 + j ----
__global__ void psroi_kernel(const float* __restrict__ fsam, const float* __restrict__ rois,
                             float* __restrict__ froi) {
    int t = blockIdx.x*blockDim.x + threadIdx.x;
    int total = NI*NROIS*245;
    if (t >= total) return;
    int c = t % 245;
    int r = (t / 245) % NROIS;
    int n = t / (245*NROIS);
    const float* ro = rois + ((size_t)n*NROIS + r)*4;
    float x1 = ro[0] * (1.f/16.f), y1 = ro[1] * (1.f/16.f);
    float x2 = ro[2] * (1.f/16.f), y2 = ro[3] * (1.f/16.f);
    float bw = fmaxf(x2-x1, 0.1f) * (1.f/7.f);
    float bh = fmaxf(y2-y1, 0.1f) * (1.f/7.f);
    int ij = c % 49;
    int i = ij / 7, j = ij % 7;
    float sx = x1 + (j + 0.5f) * bw;
    float sy = y1 + (i + 0.5f) * bh;
    float x = fminf(fmaxf(sx, 0.f), 19.f);
    float y = fminf(fmaxf(sy, 0.f), 19.f);
    int y0 = min(max((int)floorf(y), 0), 18);
    int x0 = min(max((int)floorf(x), 0), 18);
    float wy = y - (float)y0;
    float wx = x - (float)x0;
    const float* f = fsam + ((size_t)n*245 + c)*400;
    float v00 = f[y0*20 + x0],     v01 = f[y0*20 + x0 + 1];
    float v10 = f[(y0+1)*20 + x0], v11 = f[(y0+1)*20 + x0 + 1];
    froi[t] = v00*(1.f-wy)*(1.f-wx) + v01*(1.f-wy)*wx + v10*wy*(1.f-wx) + v11*wy*wx;
}

// ---- FC1: (1600,245) @ (245,1024) + b, relu ----
__global__ void fc1_kernel(const float* __restrict__ froi, const float* __restrict__ fcw,
                           const float* __restrict__ fcb, float* __restrict__ h) {
    int t = blockIdx.x*blockDim.x + threadIdx.x;
    int total = NI*NROIS*1024;
    if (t >= total) return;
    int k = t % 1024;
    int row = t / 1024;
    const float* fr = froi + (size_t)row*245;
    float s = fcb[k];
    for (int c = 0; c < 245; c++) s += fr[c] * fcw[c*1024 + k];
    h[t] = fmaxf(s, 0.f);
}

// ---- FC2 heads: sub_cls (21) and sub_reg (4) ----
__global__ void fc2_kernel(const float* __restrict__ h, const float* __restrict__ cfw,
                           const float* __restrict__ cfb, const float* __restrict__ rfw,
                           const float* __restrict__ rfb, float* __restrict__ out_cls,
                           float* __restrict__ out_reg) {
    int t = blockIdx.x*blockDim.x + threadIdx.x;
    int total = NI*NROIS*25;
    if (t >= total) return;
    int m = t % 25;
    int row = t / 25;
    const float* hr = h + (size_t)row*1024;
    if (m < 21) {
        float s = cfb[m];
        for (int k = 0; k < 1024; k++) s += hr[k] * cfw[k*21 + m];
        out_cls[row*21 + m] = s;
    } else {
        int mm = m - 21;
        float s = rfb[mm];
        for (int k = 0; k < 1024; k++) s += hr[k] * rfw[k*4 + mm];
        out_reg[row*4 + mm] = s;
    }
}

extern "C" void kernel_launch(void* const* d_in, const int* in_sizes, int n_in,
                              void* d_out, int out_size) {
    const float* x      = (const float*)d_in[0];
    const float* w1     = (const float*)d_in[1];
    const float* b1     = (const float*)d_in[2];
    const float* w2     = (const float*)d_in[3];
    const float* b2     = (const float*)d_in[4];
    const float* w3     = (const float*)d_in[5];
    const float* b3     = (const float*)d_in[6];
    const float* w4     = (const float*)d_in[7];
    const float* b4     = (const float*)d_in[8];
    const float* cem_w4 = (const float*)d_in[9];
    const float* cem_b4 = (const float*)d_in[10];
    const float* cem_w5 = (const float*)d_in[11];
    const float* cem_b5 = (const float*)d_in[12];
    const float* cem_wg = (const float*)d_in[13];
    const float* cem_bg = (const float*)d_in[14];
    const float* rpn_dw = (const float*)d_in[15];
    const float* rpn_dwb= (const float*)d_in[16];
    const float* rpn_pw = (const float*)d_in[17];
    const float* rpn_pwb= (const float*)d_in[18];
    const float* cls_w  = (const float*)d_in[19];
    const float* cls_b  = (const float*)d_in[20];
    const float* reg_w  = (const float*)d_in[21];
    const float* reg_b  = (const float*)d_in[22];
    const float* sam_w  = (const float*)d_in[23];
    const float* sam_b  = (const float*)d_in[24];
    const float* fc_w   = (const float*)d_in[25];
    const float* fc_b   = (const float*)d_in[26];
    const float* cls_fw = (const float*)d_in[27];
    const float* cls_fb = (const float*)d_in[28];
    const float* reg_fw = (const float*)d_in[29];
    const float* reg_fb = (const float*)d_in[30];
    float* out = (float*)d_out;

    float* buf = nullptr;
    cudaGetSymbolAddress((void**)&buf, g_buf);
    unsigned long long* keys = nullptr;
    cudaGetSymbolAddress((void**)&keys, g_keys);

    cudaFuncSetAttribute(sort_kernel, cudaFuncAttributeMaxDynamicSharedMemorySize,
                         SORTN * (int)sizeof(unsigned long long));

    const int TB = 256;

    // backbone
    conv3x3s2_relu<<<CDIV(NI*24*160*160, TB), TB>>>(x, w1, b1, buf+O_C1, 3, 320, 24, 160);
    maxpool3s2<<<CDIV(NI*24*80*80, TB), TB>>>(buf+O_C1, buf+O_P1, 24, 160, 80);
    conv3x3s2_relu<<<CDIV(NI*132*40*40, TB), TB>>>(buf+O_P1, w2, b2, buf+O_C3, 24, 80, 132, 40);
    conv3x3s2_relu<<<CDIV(NI*264*20*20, TB), TB>>>(buf+O_C3, w3, b3, buf+O_C4, 132, 40, 264, 20);
    conv3x3s2_relu<<<CDIV(NI*528*10*10, TB), TB>>>(buf+O_C4, w4, b4, buf+O_C5, 264, 20, 528, 10);

    // CEM
    gap_kernel<<<CDIV(NI*528, TB), TB>>>(buf+O_C5, buf+O_GLB);
    gfc_kernel<<<CDIV(NI*245, TB), TB>>>(buf+O_GLB, cem_wg, cem_bg, buf+O_GFC);
    conv1x1<<<CDIV(NI*245*100, TB), TB>>>(buf+O_C5, cem_w5, cem_b5, buf+O_CEM5, 528, 245, 100, 0);
    fcem_kernel<<<CDIV(NI*245*400, TB), TB>>>(buf+O_C4, cem_w4, cem_b4, buf+O_GFC, buf+O_CEM5, buf+O_FCEM);

    // RPN
    dw5_kernel<<<CDIV(NI*245*400, TB), TB>>>(buf+O_FCEM, rpn_dw, rpn_dwb, buf+O_T);
    conv1x1<<<CDIV(NI*256*400, TB), TB>>>(buf+O_T, rpn_pw, rpn_pwb, buf+O_FRPN, 245, 256, 400, 1);
    conv1x1<<<CDIV(NI*50*400, TB), TB>>>(buf+O_FRPN, cls_w, cls_b, buf+O_CLS, 256, 50, 400, 0);
    conv1x1<<<CDIV(NI*100*400, TB), TB>>>(buf+O_FRPN, reg_w, reg_b, buf+O_REG, 256, 100, 400, 0);
    fsam_kernel<<<CDIV(NI*245*400, TB), TB>>>(buf+O_FRPN, sam_w, sam_b, buf+O_FCEM, buf+O_FSAM);

    // proposals
    scorebox_kernel<<<CDIV(NI*SORTN, TB), TB>>>(buf+O_CLS, buf+O_REG, buf+O_BOX, keys);
    sort_kernel<<<NI, 1024, SORTN*sizeof(unsigned long long)>>>(keys, buf+O_BOX, buf+O_BK);
    nms_kernel<<<NI, 256>>>(buf+O_BK, buf+O_ROI, out + (size_t)NI*NROIS*21 + (size_t)NI*NROIS*4);

    // head
    psroi_kernel<<<CDIV(NI*NROIS*245, TB), TB>>>(buf+O_FSAM, buf+O_ROI, buf+O_FROI);
    fc1_kernel<<<CDIV(NI*NROIS*1024, TB), TB>>>(buf+O_FROI, fc_w, fc_b, buf+O_H);
    fc2_kernel<<<CDIV(NI*NROIS*25, TB), TB>>>(buf+O_H, cls_fw, cls_fb, reg_fw, reg_fb,
                                              out, out + (size_t)NI*NROIS*21);
}

// round 3
// speedup vs baseline: 1.2432x; 1.2432x over previous
#include <cuda_runtime.h>
#include <math.h>

#define CDIV(a,b) (((a)+(b)-1)/(b))

constexpr int NI     = 8;
constexpr int NANCH  = 10000;
constexpr int SORTN  = 16384;
constexpr int PRENMS = 1000;
constexpr int NROIS  = 200;

// ---- scratch layout (floats) ----
constexpr size_t O_C1  = 0;                constexpr size_t S_C1  = (size_t)NI*24*160*160;
constexpr size_t O_P1  = O_C1 + S_C1;      constexpr size_t S_P1  = (size_t)NI*24*80*80;
constexpr size_t O_C3  = O_P1 + S_P1;      constexpr size_t S_C3  = (size_t)NI*132*40*40;
constexpr size_t O_C4  = O_C3 + S_C3;      constexpr size_t S_C4  = (size_t)NI*264*20*20;
constexpr size_t O_C5  = O_C4 + S_C4;      constexpr size_t S_C5  = (size_t)NI*528*10*10;
constexpr size_t O_GLB = O_C5 + S_C5;      constexpr size_t S_GLB = (size_t)NI*528;
constexpr size_t O_GFC = O_GLB + S_GLB;    constexpr size_t S_GFC = (size_t)NI*245;
constexpr size_t O_CEM5= O_GFC + S_GFC;    constexpr size_t S_CEM5= (size_t)NI*245*100;
constexpr size_t O_FCEM= O_CEM5 + S_CEM5;  constexpr size_t S_FCEM= (size_t)NI*245*400;
constexpr size_t O_T   = O_FCEM + S_FCEM;  constexpr size_t S_T   = S_FCEM;
constexpr size_t O_FRPN= O_T + S_T;        constexpr size_t S_FRPN= (size_t)NI*256*400;
constexpr size_t O_CLS = O_FRPN + S_FRPN;  constexpr size_t S_CLS = (size_t)NI*50*400;
constexpr size_t O_REG = O_CLS + S_CLS;    constexpr size_t S_REG = (size_t)NI*100*400;
constexpr size_t O_FSAM= O_REG + S_REG;    constexpr size_t S_FSAM= S_FCEM;
constexpr size_t O_BOX = O_FSAM + S_FSAM;  constexpr size_t S_BOX = (size_t)NI*NANCH*4;
constexpr size_t O_BK  = O_BOX + S_BOX;    constexpr size_t S_BK  = (size_t)NI*PRENMS*4;
constexpr size_t O_ROI = O_BK + S_BK;      constexpr size_t S_ROI = (size_t)NI*NROIS*4;
constexpr size_t O_FROI= O_ROI + S_ROI;    constexpr size_t S_FROI= (size_t)NI*NROIS*245;
constexpr size_t O_H   = O_FROI + S_FROI;  constexpr size_t S_H   = (size_t)NI*NROIS*1024;
constexpr size_t TOTAL = O_H + S_H;

__device__ float g_buf[TOTAL];
__device__ unsigned long long g_keys[(size_t)NI*SORTN];

// =================== tiled 3x3 stride-2 conv + relu ===================
template<int CIN, int HIN, int HOUT, int ROWS, int OC_TILE, int IC_CHUNK, int NT>
__global__ void __launch_bounds__(NT)
conv_tiled(const float* __restrict__ in, const float* __restrict__ w,
           const float* __restrict__ bias, float* __restrict__ out, int Cout) {
    constexpr int IN_ROWS = 2*ROWS + 1;
    constexpr int IN_W = HIN + 1;  // +1 zero pad right (SAME, pad_hi=1)
    __shared__ float s_in[IC_CHUNK][IN_ROWS][IN_W];
    __shared__ float s_w[OC_TILE][IC_CHUNK][9];
    int n   = blockIdx.x;
    int oct = blockIdx.y;
    int oy0 = blockIdx.z * ROWS;
    int iy0 = 2*oy0;
    int tid = threadIdx.x;
    int ox = tid % HOUT;
    int lr = tid / HOUT;
    bool active = (lr < ROWS);

    float acc[OC_TILE];
    #pragma unroll
    for (int o = 0; o < OC_TILE; o++) acc[o] = 0.f;

    const float* ip = in + (size_t)n*CIN*HIN*HIN;
    for (int ic0 = 0; ic0 < CIN; ic0 += IC_CHUNK) {
        for (int idx = tid; idx < IC_CHUNK*IN_ROWS*IN_W; idx += NT) {
            int c   = idx / (IN_ROWS*IN_W);
            int rem = idx % (IN_ROWS*IN_W);
            int r   = rem / IN_W;
            int col = rem % IN_W;
            int gy = iy0 + r;
            float v = 0.f;
            if (gy < HIN && col < HIN)
                v = ip[((size_t)(ic0+c))*HIN*HIN + gy*HIN + col];
            s_in[c][r][col] = v;
        }
        for (int idx = tid; idx < OC_TILE*IC_CHUNK*9; idx += NT) {
            int o   = idx / (IC_CHUNK*9);
            int rem = idx % (IC_CHUNK*9);
            s_w[o][rem/9][rem%9] = w[((size_t)(oct*OC_TILE + o)*CIN + ic0 + rem/9)*9 + rem%9];
        }
        __syncthreads();
        if (active) {
            #pragma unroll
            for (int c = 0; c < IC_CHUNK; c++) {
                float v[9];
                #pragma unroll
                for (int ky = 0; ky < 3; ky++)
                    #pragma unroll
                    for (int kx = 0; kx < 3; kx++)
                        v[ky*3+kx] = s_in[c][2*lr+ky][2*ox+kx];
                #pragma unroll
                for (int o = 0; o < OC_TILE; o++) {
                    #pragma unroll
                    for (int k = 0; k < 9; k++)
                        acc[o] = fmaf(v[k], s_w[o][c][k], acc[o]);
                }
            }
        }
        __syncthreads();
    }
    if (active) {
        int oy = oy0 + lr;
        #pragma unroll
        for (int o = 0; o < OC_TILE; o++) {
            int oc = oct*OC_TILE + o;
            out[(((size_t)n*Cout + oc)*HOUT + oy)*HOUT + ox] = fmaxf(acc[o] + bias[oc], 0.f);
        }
    }
}

// =================== tiled 1x1 conv (GEMM) ===================
// MODE 0: plain, 1: relu, 2: fsam (out = extra1 * sigmoid(s)),
// MODE 3: fcem (s += extra1[n*245+oc] + up2(extra2))
template<int CIN, int P, int OC_TILE, int IC_CHUNK, int NT, int MODE>
__global__ void __launch_bounds__(NT)
conv1x1_tiled(const float* __restrict__ in, const float* __restrict__ w,
              const float* __restrict__ bias, float* __restrict__ out,
              int Cout, const float* __restrict__ extra1,
              const float* __restrict__ extra2) {
    __shared__ float s_in[IC_CHUNK][P];
    __shared__ float s_w[OC_TILE][IC_CHUNK];
    int n   = blockIdx.x;
    int oct = blockIdx.y;
    int tid = threadIdx.x;
    bool active = (tid < P);

    float acc[OC_TILE];
    #pragma unroll
    for (int o = 0; o < OC_TILE; o++) acc[o] = 0.f;

    const float* ip = in + (size_t)n*CIN*P;
    for (int ic0 = 0; ic0 < CIN; ic0 += IC_CHUNK) {
        for (int idx = tid; idx < IC_CHUNK*P; idx += NT) {
            int c = idx / P, p = idx % P;
            s_in[c][p] = (ic0 + c < CIN) ? ip[(size_t)(ic0+c)*P + p] : 0.f;
        }
        for (int idx = tid; idx < OC_TILE*IC_CHUNK; idx += NT) {
            int o = idx / IC_CHUNK, c = idx % IC_CHUNK;
            s_w[o][c] = (ic0 + c < CIN) ? w[(size_t)(oct*OC_TILE + o)*CIN + ic0 + c] : 0.f;
        }
        __syncthreads();
        if (active) {
            #pragma unroll
            for (int c = 0; c < IC_CHUNK; c++) {
                float v = s_in[c][tid];
                #pragma unroll
                for (int o = 0; o < OC_TILE; o++)
                    acc[o] = fmaf(v, s_w[o][c], acc[o]);
            }
        }
        __syncthreads();
    }
    if (active) {
        #pragma unroll
        for (int o = 0; o < OC_TILE; o++) {
            int oc = oct*OC_TILE + o;
            float s = acc[o] + bias[oc];
            size_t oidx = ((size_t)n*Cout + oc)*P + tid;
            if (MODE == 1) s = fmaxf(s, 0.f);
            else if (MODE == 2) s = extra1[oidx] * (1.f / (1.f + expf(-s)));
            else if (MODE == 3) {
                int y = tid / 20, x = tid % 20;
                s += extra1[n*245 + oc] + extra2[((size_t)n*245 + oc)*100 + (y/2)*10 + (x/2)];
            }
            out[oidx] = s;
        }
    }
}

// =================== 3x3 stride-2 maxpool SAME ===================
__global__ void maxpool3s2(const float* __restrict__ in, float* __restrict__ out,
                           int C, int Hin, int Hout) {
    int t = blockIdx.x*blockDim.x + threadIdx.x;
    int total = NI*C*Hout*Hout;
    if (t >= total) return;
    int ox = t % Hout;
    int oy = (t / Hout) % Hout;
    int nc = t / (Hout*Hout);
    const float* ip = in + (size_t)nc*Hin*Hin;
    float m = -INFINITY;
    #pragma unroll
    for (int ky = 0; ky < 3; ky++) {
        int iy = 2*oy + ky;
        if (iy >= Hin) continue;
        #pragma unroll
        for (int kx = 0; kx < 3; kx++) {
            int ix = 2*ox + kx;
            if (ix >= Hin) continue;
            m = fmaxf(m, ip[iy*Hin+ix]);
        }
    }
    out[t] = m;
}

__global__ void gap_kernel(const float* __restrict__ c5, float* __restrict__ glb) {
    int t = blockIdx.x*blockDim.x + threadIdx.x;
    if (t >= NI*528) return;
    const float* p = c5 + (size_t)t*100;
    float s = 0.f;
    for (int i = 0; i < 100; i++) s += p[i];
    glb[t] = s / 100.f;
}

__global__ void gfc_kernel(const float* __restrict__ glb, const float* __restrict__ wg,
                           const float* __restrict__ bg, float* __restrict__ gfc) {
    int t = blockIdx.x*blockDim.x + threadIdx.x;
    if (t >= NI*245) return;
    int k = t % 245, n = t / 245;
    float s = bg[k];
    const float* g = glb + n*528;
    for (int c = 0; c < 528; c++) s += g[c] * wg[c*245 + k];
    gfc[t] = s;
}

// ---- depthwise 5x5 SAME + relu ----
__global__ void dw5_kernel(const float* __restrict__ in, const float* __restrict__ w,
                           const float* __restrict__ bias, float* __restrict__ out) {
    int t = blockIdx.x*blockDim.x + threadIdx.x;
    int total = NI*245*400;
    if (t >= total) return;
    int p = t % 400;
    int k = (t / 400) % 245;
    int y = p / 20, x = p % 20;
    const float* ip = in + (size_t)(t/400)*400;
    const float* wk = w + k*25;
    float s = bias[k];
    #pragma unroll
    for (int ky = 0; ky < 5; ky++) {
        int iy = y - 2 + ky;
        if (iy < 0 || iy >= 20) continue;
        #pragma unroll
        for (int kx = 0; kx < 5; kx++) {
            int ix = x - 2 + kx;
            if (ix < 0 || ix >= 20) continue;
            s += ip[iy*20+ix] * wk[ky*5+kx];
        }
    }
    out[t] = fmaxf(s, 0.f);
}

// ---- scores + decoded boxes + sort keys ----
__global__ void scorebox_kernel(const float* __restrict__ clsmap, const float* __restrict__ regmap,
                                float* __restrict__ boxes, unsigned long long* __restrict__ keys) {
    int t = blockIdx.x*blockDim.x + threadIdx.x;
    if (t >= NI*SORTN) return;
    int i = t % SORTN;
    int n = t / SORTN;
    if (i >= NANCH) { keys[t] = 0ull; return; }
    int a = i % 25;
    int x = (i / 25) % 20;
    int y = i / 500;
    int p = y*20 + x;
    const float* cm = clsmap + (size_t)n*50*400;
    float c0 = cm[(a*2  )*400 + p];
    float c1 = cm[(a*2+1)*400 + p];
    float score = 1.f / (1.f + expf(c0 - c1));
    const float* rm = regmap + (size_t)n*100*400;
    float d0 = rm[(a*4  )*400 + p];
    float d1 = rm[(a*4+1)*400 + p];
    float d2 = rm[(a*4+2)*400 + p];
    float d3 = rm[(a*4+3)*400 + p];
    const float scales[5] = {32.f, 64.f, 128.f, 256.f, 512.f};
    const float ratios[5] = {0.5f, 0.75f, 1.0f, 4.0f/3.0f, 2.0f};
    int si = a / 5, ri = a % 5;
    float sq = sqrtf(ratios[ri]);
    float aw = scales[si] / sq;
    float ah = scales[si] * sq;
    float acx = (x + 0.5f) * 16.f;
    float acy = (y + 0.5f) * 16.f;
    float cx = d0*aw + acx;
    float cy = d1*ah + acy;
    float w  = expf(d2) * aw;
    float h  = expf(d3) * ah;
    float* b = boxes + ((size_t)n*NANCH + i)*4;
    b[0] = fminf(fmaxf(cx - 0.5f*w, 0.f), 319.f);
    b[1] = fminf(fmaxf(cy - 0.5f*h, 0.f), 319.f);
    b[2] = fminf(fmaxf(cx + 0.5f*w, 0.f), 319.f);
    b[3] = fminf(fmaxf(cy + 0.5f*h, 0.f), 319.f);
    unsigned sb = __float_as_uint(score);
    keys[t] = ((unsigned long long)sb << 32) | (unsigned long long)(0xFFFFFFFFu - (unsigned)i);
}

// ---- per-image bitonic sort (descending) over 16384 keys; gather top-1000 boxes ----
__global__ void __launch_bounds__(1024)
sort_kernel(unsigned long long* __restrict__ keys,
            const float* __restrict__ boxes, float* __restrict__ bk) {
    extern __shared__ unsigned long long sk[];
    int n = blockIdx.x;
    unsigned long long* g = keys + (size_t)n*SORTN;
    for (int i = threadIdx.x; i < SORTN; i += blockDim.x) sk[i] = g[i];
    __syncthreads();
    for (int size = 2; size <= SORTN; size <<= 1) {
        for (int stride = size >> 1; stride > 0; stride >>= 1) {
            for (int t = threadIdx.x; t < SORTN/2; t += blockDim.x) {
                int lo = ((t & ~(stride-1)) << 1) | (t & (stride-1));
                int hi = lo + stride;
                unsigned long long a = sk[lo], c = sk[hi];
                bool desc = ((lo & size) == 0);
                bool sw = desc ? (a < c) : (a > c);
                if (sw) { sk[lo] = c; sk[hi] = a; }
            }
            __syncthreads();
        }
    }
    for (int j = threadIdx.x; j < PRENMS; j += blockDim.x) {
        unsigned idx = 0xFFFFFFFFu - (unsigned)(sk[j] & 0xFFFFFFFFull);
        const float* src = boxes + ((size_t)n*NANCH + idx)*4;
        float* dst = bk + ((size_t)n*PRENMS + j)*4;
        dst[0] = src[0]; dst[1] = src[1]; dst[2] = src[2]; dst[3] = src[3];
    }
}

// ---- sequential NMS + stable partition -> 200 rois ----
__global__ void nms_kernel(const float* __restrict__ bk, float* __restrict__ rois,
                           float* __restrict__ out_rois) {
    __shared__ float4 box[PRENMS];
    __shared__ float  area[PRENMS];
    __shared__ int    supp[PRENMS];
    __shared__ int    order[NROIS];
    int n = blockIdx.x;
    const float* b = bk + (size_t)n*PRENMS*4;
    for (int i = threadIdx.x; i < PRENMS; i += blockDim.x) {
        float x1 = b[i*4], y1 = b[i*4+1], x2 = b[i*4+2], y2 = b[i*4+3];
        box[i] = make_float4(x1, y1, x2, y2);
        area[i] = (x2-x1)*(y2-y1);
        supp[i] = 0;
    }
    __syncthreads();
    for (int i = 0; i < PRENMS; i++) {
        if (!supp[i]) {
            float4 bi = box[i];
            float ai = area[i];
            for (int j = i + 1 + threadIdx.x; j < PRENMS; j += blockDim.x) {
                float ix1 = fmaxf(bi.x, box[j].x);
                float iy1 = fmaxf(bi.y, box[j].y);
                float ix2 = fminf(bi.z, box[j].z);
                float iy2 = fminf(bi.w, box[j].w);
                float inter = fmaxf(ix2-ix1, 0.f) * fmaxf(iy2-iy1, 0.f);
                float iou = inter / (ai + area[j] - inter + 1e-9f);
                if (iou > 0.7f) supp[j] = 1;
            }
        }
        __syncthreads();
    }
    if (threadIdx.x == 0) {
        int c = 0;
        for (int i = 0; i < PRENMS && c < NROIS; i++) if (!supp[i]) order[c++] = i;
        for (int i = 0; i < PRENMS && c < NROIS; i++) if ( supp[i]) order[c++] = i;
    }
    __syncthreads();
    for (int r = threadIdx.x; r < NROIS; r += blockDim.x) {
        float4 bb = box[order[r]];
        float* dst = rois + ((size_t)n*NROIS + r)*4;
        dst[0] = bb.x; dst[1] = bb.y; dst[2] = bb.z; dst[3] = bb.w;
        float* o = out_rois + ((size_t)n*NROIS + r)*4;
        o[0] = bb.x; o[1] = bb.y; o[2] = bb.z; o[3] = bb.w;
    }
}

// ---- PSRoI pooling ----
__global__ void psroi_kernel(const float* __restrict__ fsam, const float* __restrict__ rois,
                             float* __restrict__ froi) {
    int t = blockIdx.x*blockDim.x + threadIdx.x;
    int total = NI*NROIS*245;
    if (t >= total) return;
    int c = t % 245;
    int r = (t / 245) % NROIS;
    int n = t / (245*NROIS);
    const float* ro = rois + ((size_t)n*NROIS + r)*4;
    float x1 = ro[0] * (1.f/16.f), y1 = ro[1] * (1.f/16.f);
    float x2 = ro[2] * (1.f/16.f), y2 = ro[3] * (1.f/16.f);
    float bw = fmaxf(x2-x1, 0.1f) * (1.f/7.f);
    float bh = fmaxf(y2-y1, 0.1f) * (1.f/7.f);
    int ij = c % 49;
    int i = ij / 7, j = ij % 7;
    float sx = x1 + (j + 0.5f) * bw;
    float sy = y1 + (i + 0.5f) * bh;
    float x = fminf(fmaxf(sx, 0.f), 19.f);
    float y = fminf(fmaxf(sy, 0.f), 19.f);
    int y0 = min(max((int)floorf(y), 0), 18);
    int x0 = min(max((int)floorf(x), 0), 18);
    float wy = y - (float)y0;
    float wx = x - (float)x0;
    const float* f = fsam + ((size_t)n*245 + c)*400;
    float v00 = f[y0*20 + x0],     v01 = f[y0*20 + x0 + 1];
    float v10 = f[(y0+1)*20 + x0], v11 = f[(y0+1)*20 + x0 + 1];
    froi[t] = v00*(1.f-wy)*(1.f-wx) + v01*(1.f-wy)*wx + v10*wy*(1.f-wx) + v11*wy*wx;
}

// ---- tiled FC1 ----
__global__ void __launch_bounds__(256)
fc1_tiled(const float* __restrict__ froi, const float* __restrict__ fcw,
          const float* __restrict__ fcb, float* __restrict__ h) {
    __shared__ float sf[16][246];
    int r0 = blockIdx.x * 16;
    int k  = blockIdx.y * 256 + threadIdx.x;
    for (int idx = threadIdx.x; idx < 16*245; idx += 256) {
        int r = idx / 245, c = idx % 245;
        sf[r][c] = froi[(size_t)(r0+r)*245 + c];
    }
    __syncthreads();
    float acc[16];
    float b = fcb[k];
    #pragma unroll
    for (int i = 0; i < 16; i++) acc[i] = b;
    for (int c = 0; c < 245; c++) {
        float wv = fcw[c*1024 + k];
        #pragma unroll
        for (int i = 0; i < 16; i++) acc[i] = fmaf(sf[i][c], wv, acc[i]);
    }
    #pragma unroll
    for (int i = 0; i < 16; i++)
        h[(size_t)(r0+i)*1024 + k] = fmaxf(acc[i], 0.f);
}

// ---- FC2 heads ----
__global__ void fc2_kernel(const float* __restrict__ h, const float* __restrict__ cfw,
                           const float* __restrict__ cfb, const float* __restrict__ rfw,
                           const float* __restrict__ rfb, float* __restrict__ out_cls,
                           float* __restrict__ out_reg) {
    int t = blockIdx.x*blockDim.x + threadIdx.x;
    int total = NI*NROIS*25;
    if (t >= total) return;
    int m = t % 25;
    int row = t / 25;
    const float* hr = h + (size_t)row*1024;
    if (m < 21) {
        float s = cfb[m];
        for (int k = 0; k < 1024; k++) s += hr[k] * cfw[k*21 + m];
        out_cls[row*21 + m] = s;
    } else {
        int mm = m - 21;
        float s = rfb[mm];
        for (int k = 0; k < 1024; k++) s += hr[k] * rfw[k*4 + mm];
        out_reg[row*4 + mm] = s;
    }
}

extern "C" void kernel_launch(void* const* d_in, const int* in_sizes, int n_in,
                              void* d_out, int out_size) {
    const float* x      = (const float*)d_in[0];
    const float* w1     = (const float*)d_in[1];
    const float* b1     = (const float*)d_in[2];
    const float* w2     = (const float*)d_in[3];
    const float* b2     = (const float*)d_in[4];
    const float* w3     = (const float*)d_in[5];
    const float* b3     = (const float*)d_in[6];
    const float* w4     = (const float*)d_in[7];
    const float* b4     = (const float*)d_in[8];
    const float* cem_w4 = (const float*)d_in[9];
    const float* cem_b4 = (const float*)d_in[10];
    const float* cem_w5 = (const float*)d_in[11];
    const float* cem_b5 = (const float*)d_in[12];
    const float* cem_wg = (const float*)d_in[13];
    const float* cem_bg = (const float*)d_in[14];
    const float* rpn_dw = (const float*)d_in[15];
    const float* rpn_dwb= (const float*)d_in[16];
    const float* rpn_pw = (const float*)d_in[17];
    const float* rpn_pwb= (const float*)d_in[18];
    const float* cls_w  = (const float*)d_in[19];
    const float* cls_b  = (const float*)d_in[20];
    const float* reg_w  = (const float*)d_in[21];
    const float* reg_b  = (const float*)d_in[22];
    const float* sam_w  = (const float*)d_in[23];
    const float* sam_b  = (const float*)d_in[24];
    const float* fc_w   = (const float*)d_in[25];
    const float* fc_b   = (const float*)d_in[26];
    const float* cls_fw = (const float*)d_in[27];
    const float* cls_fb = (const float*)d_in[28];
    const float* reg_fw = (const float*)d_in[29];
    const float* reg_fb = (const float*)d_in[30];
    float* out = (float*)d_out;

    float* buf = nullptr;
    cudaGetSymbolAddress((void**)&buf, g_buf);
    unsigned long long* keys = nullptr;
    cudaGetSymbolAddress((void**)&keys, g_keys);

    cudaFuncSetAttribute(sort_kernel, cudaFuncAttributeMaxDynamicSharedMemorySize,
                         SORTN * (int)sizeof(unsigned long long));

    const int TB = 256;

    // backbone (tiled)
    conv_tiled<3,320,160, 2,24,3,320><<<dim3(8,1,80), 320>>>(x, w1, b1, buf+O_C1, 24);
    maxpool3s2<<<CDIV(NI*24*80*80, TB), TB>>>(buf+O_C1, buf+O_P1, 24, 160, 80);
    conv_tiled<24,80,40, 10,12,4,400><<<dim3(8,11,4), 400>>>(buf+O_P1, w2, b2, buf+O_C3, 132);
    conv_tiled<132,40,20, 20,8,4,400><<<dim3(8,33,1), 400>>>(buf+O_C3, w3, b3, buf+O_C4, 264);
    conv_tiled<264,20,10, 10,16,8,128><<<dim3(8,33,1), 128>>>(buf+O_C4, w4, b4, buf+O_C5, 528);

    // CEM
    gap_kernel<<<CDIV(NI*528, TB), TB>>>(buf+O_C5, buf+O_GLB);
    gfc_kernel<<<CDIV(NI*245, TB), TB>>>(buf+O_GLB, cem_wg, cem_bg, buf+O_GFC);
    conv1x1_tiled<528,100,35,16,100,0><<<dim3(8,7), 100>>>(buf+O_C5, cem_w5, cem_b5,
                                                           buf+O_CEM5, 245, nullptr, nullptr);
    conv1x1_tiled<264,400,35,8,400,3><<<dim3(8,7), 400>>>(buf+O_C4, cem_w4, cem_b4,
                                                          buf+O_FCEM, 245, buf+O_GFC, buf+O_CEM5);

    // RPN
    dw5_kernel<<<CDIV(NI*245*400, TB), TB>>>(buf+O_FCEM, rpn_dw, rpn_dwb, buf+O_T);
    conv1x1_tiled<245,400,32,16,400,1><<<dim3(8,8), 400>>>(buf+O_T, rpn_pw, rpn_pwb,
                                                           buf+O_FRPN, 256, nullptr, nullptr);
    conv1x1_tiled<256,400,25,16,400,0><<<dim3(8,2), 400>>>(buf+O_FRPN, cls_w, cls_b,
                                                           buf+O_CLS, 50, nullptr, nullptr);
    conv1x1_tiled<256,400,25,16,400,0><<<dim3(8,4), 400>>>(buf+O_FRPN, reg_w, reg_b,
                                                           buf+O_REG, 100, nullptr, nullptr);
    conv1x1_tiled<256,400,35,16,400,2><<<dim3(8,7), 400>>>(buf+O_FRPN, sam_w, sam_b,
                                                           buf+O_FSAM, 245, buf+O_FCEM, nullptr);

    // proposals
    scorebox_kernel<<<CDIV(NI*SORTN, TB), TB>>>(buf+O_CLS, buf+O_REG, buf+O_BOX, keys);
    sort_kernel<<<NI, 1024, SORTN*sizeof(unsigned long long)>>>(keys, buf+O_BOX, buf+O_BK);
    nms_kernel<<<NI, 256>>>(buf+O_BK, buf+O_ROI, out + (size_t)NI*NROIS*21 + (size_t)NI*NROIS*4);

    // head
    psroi_kernel<<<CDIV(NI*NROIS*245, TB), TB>>>(buf+O_FSAM, buf+O_ROI, buf+O_FROI);
    fc1_tiled<<<dim3(100,4), 256>>>(buf+O_FROI, fc_w, fc_b, buf+O_H);
    fc2_kernel<<<CDIV(NI*NROIS*25, TB), TB>>>(buf+O_H, cls_fw, cls_fb, reg_fw, reg_fb,
                                              out, out + (size_t)NI*NROIS*21);
}

// round 4
// speedup vs baseline: 1.7780x; 1.4301x over previous
#include <cuda_runtime.h>
#include <math.h>

#define CDIV(a,b) (((a)+(b)-1)/(b))

constexpr int NI     = 8;
constexpr int NANCH  = 10000;
constexpr int SORTN  = 16384;
constexpr int PRENMS = 1000;
constexpr int NROIS  = 200;

// ---- scratch layout (floats) ----
constexpr size_t O_C1  = 0;                constexpr size_t S_C1  = (size_t)NI*24*160*160;
constexpr size_t O_P1  = O_C1 + S_C1;      constexpr size_t S_P1  = (size_t)NI*24*80*80;
constexpr size_t O_C3  = O_P1 + S_P1;      constexpr size_t S_C3  = (size_t)NI*132*40*40;
constexpr size_t O_C4  = O_C3 + S_C3;      constexpr size_t S_C4  = (size_t)NI*264*20*20;
constexpr size_t O_C5  = O_C4 + S_C4;      constexpr size_t S_C5  = (size_t)NI*528*10*10;
constexpr size_t O_GLB = O_C5 + S_C5;      constexpr size_t S_GLB = (size_t)NI*528;
constexpr size_t O_GFC = O_GLB + S_GLB;    constexpr size_t S_GFC = (size_t)NI*245;
constexpr size_t O_CEM5= O_GFC + S_GFC;    constexpr size_t S_CEM5= (size_t)NI*245*100;
constexpr size_t O_FCEM= O_CEM5 + S_CEM5;  constexpr size_t S_FCEM= (size_t)NI*245*400;
constexpr size_t O_T   = O_FCEM + S_FCEM;  constexpr size_t S_T   = S_FCEM;
constexpr size_t O_FRPN= O_T + S_T;        constexpr size_t S_FRPN= (size_t)NI*256*400;
constexpr size_t O_CLS = O_FRPN + S_FRPN;  constexpr size_t S_CLS = (size_t)NI*50*400;
constexpr size_t O_REG = O_CLS + S_CLS;    constexpr size_t S_REG = (size_t)NI*100*400;
constexpr size_t O_FSAM= O_REG + S_REG;    constexpr size_t S_FSAM= S_FCEM;
constexpr size_t O_BOX = O_FSAM + S_FSAM;  constexpr size_t S_BOX = (size_t)NI*NANCH*4;
constexpr size_t O_BK  = O_BOX + S_BOX;    constexpr size_t S_BK  = (size_t)NI*PRENMS*4;
constexpr size_t O_ROI = O_BK + S_BK;      constexpr size_t S_ROI = (size_t)NI*NROIS*4;
constexpr size_t O_FROI= O_ROI + S_ROI;    constexpr size_t S_FROI= (size_t)245*NI*NROIS; // transposed [245][1600]
constexpr size_t O_H   = O_FROI + S_FROI;  constexpr size_t S_H   = (size_t)NI*NROIS*1024;
constexpr size_t O_COL = O_H + S_H;        constexpr size_t S_COL = (size_t)NI*27*160*160; // max im2col (conv1)
constexpr size_t TOTAL = O_COL + S_COL;

__device__ float g_buf[TOTAL];
__device__ unsigned long long g_keys[(size_t)NI*SORTN];

// =================== im2col for 3x3 stride-2 SAME conv ===================
// out[n][ic*9+ky*3+kx][oy*Hout+ox] = in[n][ic][2*oy+ky][2*ox+kx] (0 beyond edge)
__global__ void im2col_kernel(const float* __restrict__ in, float* __restrict__ out,
                              int Cin, int Hin, int Hout, int total) {
    int idx = blockIdx.x*blockDim.x + threadIdx.x;
    if (idx >= total) return;
    int P = Hout*Hout;
    int p = idx % P;
    int k = (idx / P) % (Cin*9);
    int n = idx / (P*Cin*9);
    int ic = k / 9, r = k % 9;
    int ky = r / 3, kx = r % 3;
    int oy = p / Hout, ox = p % Hout;
    int iy = 2*oy + ky, ix = 2*ox + kx;
    float v = 0.f;
    if (iy < Hin && ix < Hin)
        v = in[(((size_t)n*Cin + ic)*Hin + iy)*Hin + ix];
    out[idx] = v;
}

// =================== unified tiled GEMM ===================
// C[m][n] = sum_k A[m][k]*B[k][n] (+bias, epilogue). 64x64 tile, 256 thr, 4x4/thread.
// MODE: 0 bias, 1 bias+relu, 2 fsam: e1*sigmoid(s), 3 fcem adds, 4 relu + transposed store C[n][m]
template<int MODE, bool TRANSA>
__global__ void __launch_bounds__(256)
gemm_tiled(const float* __restrict__ A, const float* __restrict__ B,
           const float* __restrict__ bias, float* __restrict__ C,
           int M, int K, int N, long sB, long sC,
           const float* __restrict__ e1, const float* __restrict__ e2) {
    __shared__ float As[16][68];
    __shared__ float Bs[16][68];
    int nimg = blockIdx.z;
    int m0 = blockIdx.y*64, n0 = blockIdx.x*64;
    const float* Bp = B + (long)nimg*sB;
    float* Cp = C + (long)nimg*sC;
    int tid = threadIdx.x;
    int tx = tid % 16, ty = tid / 16;
    float acc[4][4] = {};
    for (int k0 = 0; k0 < K; k0 += 16) {
        if (!TRANSA) {
            int r = tid >> 2, c = (tid & 3) * 4;
            #pragma unroll
            for (int i = 0; i < 4; i++) {
                int mm = m0 + r, kk = k0 + c + i;
                As[c+i][r] = (mm < M && kk < K) ? A[(long)mm*K + kk] : 0.f;
            }
        } else {
            int r = tid >> 4, c = (tid & 15) * 4;
            #pragma unroll
            for (int i = 0; i < 4; i++) {
                int kk = k0 + r, mm = m0 + c + i;
                As[r][c+i] = (mm < M && kk < K) ? A[(long)kk*M + mm] : 0.f;
            }
        }
        {
            int r = tid >> 4, c = (tid & 15) * 4;
            #pragma unroll
            for (int i = 0; i < 4; i++) {
                int kk = k0 + r, nn = n0 + c + i;
                Bs[r][c+i] = (kk < K && nn < N) ? Bp[(long)kk*N + nn] : 0.f;
            }
        }
        __syncthreads();
        #pragma unroll
        for (int kk = 0; kk < 16; kk++) {
            float4 av = *reinterpret_cast<const float4*>(&As[kk][ty*4]);
            float4 bv = *reinterpret_cast<const float4*>(&Bs[kk][tx*4]);
            float a[4] = {av.x, av.y, av.z, av.w};
            float b[4] = {bv.x, bv.y, bv.z, bv.w};
            #pragma unroll
            for (int i = 0; i < 4; i++)
                #pragma unroll
                for (int j = 0; j < 4; j++)
                    acc[i][j] = fmaf(a[i], b[j], acc[i][j]);
        }
        __syncthreads();
    }
    #pragma unroll
    for (int i = 0; i < 4; i++) {
        int m = m0 + ty*4 + i;
        if (m >= M) continue;
        float bv = bias[m];
        #pragma unroll
        for (int j = 0; j < 4; j++) {
            int n = n0 + tx*4 + j;
            if (n >= N) continue;
            float s = acc[i][j] + bv;
            if (MODE == 1) s = fmaxf(s, 0.f);
            else if (MODE == 2) {
                s = e1[(long)nimg*sC + (long)m*N + n] * (1.f/(1.f + expf(-s)));
            } else if (MODE == 3) {
                int y = n / 20, x = n % 20;
                s += e1[nimg*245 + m] + e2[((long)nimg*245 + m)*100 + (y/2)*10 + (x/2)];
            }
            if (MODE == 4) {
                s = fmaxf(s, 0.f);
                Cp[(long)n*M + m] = s;
            } else {
                Cp[(long)m*N + n] = s;
            }
        }
    }
}

// =================== 3x3 stride-2 maxpool SAME ===================
__global__ void maxpool3s2(const float* __restrict__ in, float* __restrict__ out,
                           int C, int Hin, int Hout) {
    int t = blockIdx.x*blockDim.x + threadIdx.x;
    int total = NI*C*Hout*Hout;
    if (t >= total) return;
    int ox = t % Hout;
    int oy = (t / Hout) % Hout;
    int nc = t / (Hout*Hout);
    const float* ip = in + (size_t)nc*Hin*Hin;
    float m = -INFINITY;
    #pragma unroll
    for (int ky = 0; ky < 3; ky++) {
        int iy = 2*oy + ky;
        if (iy >= Hin) continue;
        #pragma unroll
        for (int kx = 0; kx < 3; kx++) {
            int ix = 2*ox + kx;
            if (ix >= Hin) continue;
            m = fmaxf(m, ip[iy*Hin+ix]);
        }
    }
    out[t] = m;
}

__global__ void gap_kernel(const float* __restrict__ c5, float* __restrict__ glb) {
    int t = blockIdx.x*blockDim.x + threadIdx.x;
    if (t >= NI*528) return;
    const float* p = c5 + (size_t)t*100;
    float s = 0.f;
    for (int i = 0; i < 100; i++) s += p[i];
    glb[t] = s / 100.f;
}

__global__ void gfc_kernel(const float* __restrict__ glb, const float* __restrict__ wg,
                           const float* __restrict__ bg, float* __restrict__ gfc) {
    int t = blockIdx.x*blockDim.x + threadIdx.x;
    if (t >= NI*245) return;
    int k = t % 245, n = t / 245;
    float s = bg[k];
    const float* g = glb + n*528;
    for (int c = 0; c < 528; c++) s += g[c] * wg[c*245 + k];
    gfc[t] = s;
}

// ---- depthwise 5x5 SAME + relu ----
__global__ void dw5_kernel(const float* __restrict__ in, const float* __restrict__ w,
                           const float* __restrict__ bias, float* __restrict__ out) {
    int t = blockIdx.x*blockDim.x + threadIdx.x;
    int total = NI*245*400;
    if (t >= total) return;
    int p = t % 400;
    int k = (t / 400) % 245;
    int y = p / 20, x = p % 20;
    const float* ip = in + (size_t)(t/400)*400;
    const float* wk = w + k*25;
    float s = bias[k];
    #pragma unroll
    for (int ky = 0; ky < 5; ky++) {
        int iy = y - 2 + ky;
        if (iy < 0 || iy >= 20) continue;
        #pragma unroll
        for (int kx = 0; kx < 5; kx++) {
            int ix = x - 2 + kx;
            if (ix < 0 || ix >= 20) continue;
            s += ip[iy*20+ix] * wk[ky*5+kx];
        }
    }
    out[t] = fmaxf(s, 0.f);
}

// ---- scores + decoded boxes + sort keys ----
__global__ void scorebox_kernel(const float* __restrict__ clsmap, const float* __restrict__ regmap,
                                float* __restrict__ boxes, unsigned long long* __restrict__ keys) {
    int t = blockIdx.x*blockDim.x + threadIdx.x;
    if (t >= NI*SORTN) return;
    int i = t % SORTN;
    int n = t / SORTN;
    if (i >= NANCH) { keys[t] = 0ull; return; }
    int a = i % 25;
    int x = (i / 25) % 20;
    int y = i / 500;
    int p = y*20 + x;
    const float* cm = clsmap + (size_t)n*50*400;
    float c0 = cm[(a*2  )*400 + p];
    float c1 = cm[(a*2+1)*400 + p];
    float score = 1.f / (1.f + expf(c0 - c1));
    const float* rm = regmap + (size_t)n*100*400;
    float d0 = rm[(a*4  )*400 + p];
    float d1 = rm[(a*4+1)*400 + p];
    float d2 = rm[(a*4+2)*400 + p];
    float d3 = rm[(a*4+3)*400 + p];
    const float scales[5] = {32.f, 64.f, 128.f, 256.f, 512.f};
    const float ratios[5] = {0.5f, 0.75f, 1.0f, 4.0f/3.0f, 2.0f};
    int si = a / 5, ri = a % 5;
    float sq = sqrtf(ratios[ri]);
    float aw = scales[si] / sq;
    float ah = scales[si] * sq;
    float acx = (x + 0.5f) * 16.f;
    float acy = (y + 0.5f) * 16.f;
    float cx = d0*aw + acx;
    float cy = d1*ah + acy;
    float w  = expf(d2) * aw;
    float h  = expf(d3) * ah;
    float* b = boxes + ((size_t)n*NANCH + i)*4;
    b[0] = fminf(fmaxf(cx - 0.5f*w, 0.f), 319.f);
    b[1] = fminf(fmaxf(cy - 0.5f*h, 0.f), 319.f);
    b[2] = fminf(fmaxf(cx + 0.5f*w, 0.f), 319.f);
    b[3] = fminf(fmaxf(cy + 0.5f*h, 0.f), 319.f);
    unsigned sb = __float_as_uint(score);
    keys[t] = ((unsigned long long)sb << 32) | (unsigned long long)(0xFFFFFFFFu - (unsigned)i);
}

// ---- per-image bitonic sort (descending) over 16384 keys; gather top-1000 boxes ----
__global__ void __launch_bounds__(1024)
sort_kernel(unsigned long long* __restrict__ keys,
            const float* __restrict__ boxes, float* __restrict__ bk) {
    extern __shared__ unsigned long long sk[];
    int n = blockIdx.x;
    unsigned long long* g = keys + (size_t)n*SORTN;
    for (int i = threadIdx.x; i < SORTN; i += blockDim.x) sk[i] = g[i];
    __syncthreads();
    for (int size = 2; size <= SORTN; size <<= 1) {
        for (int stride = size >> 1; stride > 0; stride >>= 1) {
            for (int t = threadIdx.x; t < SORTN/2; t += blockDim.x) {
                int lo = ((t & ~(stride-1)) << 1) | (t & (stride-1));
                int hi = lo + stride;
                unsigned long long a = sk[lo], c = sk[hi];
                bool desc = ((lo & size) == 0);
                bool sw = desc ? (a < c) : (a > c);
                if (sw) { sk[lo] = c; sk[hi] = a; }
            }
            __syncthreads();
        }
    }
    for (int j = threadIdx.x; j < PRENMS; j += blockDim.x) {
        unsigned idx = 0xFFFFFFFFu - (unsigned)(sk[j] & 0xFFFFFFFFull);
        const float* src = boxes + ((size_t)n*NANCH + idx)*4;
        float* dst = bk + ((size_t)n*PRENMS + j)*4;
        dst[0] = src[0]; dst[1] = src[1]; dst[2] = src[2]; dst[3] = src[3];
    }
}

// ---- sequential NMS + stable partition -> 200 rois ----
__global__ void nms_kernel(const float* __restrict__ bk, float* __restrict__ rois,
                           float* __restrict__ out_rois) {
    __shared__ float4 box[PRENMS];
    __shared__ float  area[PRENMS];
    __shared__ int    supp[PRENMS];
    __shared__ int    order[NROIS];
    int n = blockIdx.x;
    const float* b = bk + (size_t)n*PRENMS*4;
    for (int i = threadIdx.x; i < PRENMS; i += blockDim.x) {
        float x1 = b[i*4], y1 = b[i*4+1], x2 = b[i*4+2], y2 = b[i*4+3];
        box[i] = make_float4(x1, y1, x2, y2);
        area[i] = (x2-x1)*(y2-y1);
        supp[i] = 0;
    }
    __syncthreads();
    for (int i = 0; i < PRENMS; i++) {
        if (!supp[i]) {
            float4 bi = box[i];
            float ai = area[i];
            for (int j = i + 1 + threadIdx.x; j < PRENMS; j += blockDim.x) {
                float ix1 = fmaxf(bi.x, box[j].x);
                float iy1 = fmaxf(bi.y, box[j].y);
                float ix2 = fminf(bi.z, box[j].z);
                float iy2 = fminf(bi.w, box[j].w);
                float inter = fmaxf(ix2-ix1, 0.f) * fmaxf(iy2-iy1, 0.f);
                float iou = inter / (ai + area[j] - inter + 1e-9f);
                if (iou > 0.7f) supp[j] = 1;
            }
        }
        __syncthreads();
    }
    if (threadIdx.x == 0) {
        int c = 0;
        for (int i = 0; i < PRENMS && c < NROIS; i++) if (!supp[i]) order[c++] = i;
        for (int i = 0; i < PRENMS && c < NROIS; i++) if ( supp[i]) order[c++] = i;
    }
    __syncthreads();
    for (int r = threadIdx.x; r < NROIS; r += blockDim.x) {
        float4 bb = box[order[r]];
        float* dst = rois + ((size_t)n*NROIS + r)*4;
        dst[0] = bb.x; dst[1] = bb.y; dst[2] = bb.z; dst[3] = bb.w;
        float* o = out_rois + ((size_t)n*NROIS + r)*4;
        o[0] = bb.x; o[1] = bb.y; o[2] = bb.z; o[3] = bb.w;
    }
}

// ---- PSRoI pooling: stores TRANSPOSED froiT[c][n*200+r] for fc1 GEMM ----
__global__ void psroi_kernel(const float* __restrict__ fsam, const float* __restrict__ rois,
                             float* __restrict__ froiT) {
    int t = blockIdx.x*blockDim.x + threadIdx.x;
    int total = NI*NROIS*245;
    if (t >= total) return;
    int c = t % 245;
    int r = (t / 245) % NROIS;
    int n = t / (245*NROIS);
    const float* ro = rois + ((size_t)n*NROIS + r)*4;
    float x1 = ro[0] * (1.f/16.f), y1 = ro[1] * (1.f/16.f);
    float x2 = ro[2] * (1.f/16.f), y2 = ro[3] * (1.f/16.f);
    float bw = fmaxf(x2-x1, 0.1f) * (1.f/7.f);
    float bh = fmaxf(y2-y1, 0.1f) * (1.f/7.f);
    int ij = c % 49;
    int i = ij / 7, j = ij % 7;
    float sx = x1 + (j + 0.5f) * bw;
    float sy = y1 + (i + 0.5f) * bh;
    float x = fminf(fmaxf(sx, 0.f), 19.f);
    float y = fminf(fmaxf(sy, 0.f), 19.f);
    int y0 = min(max((int)floorf(y), 0), 18);
    int x0 = min(max((int)floorf(x), 0), 18);
    float wy = y - (float)y0;
    float wx = x - (float)x0;
    const float* f = fsam + ((size_t)n*245 + c)*400;
    float v00 = f[y0*20 + x0],     v01 = f[y0*20 + x0 + 1];
    float v10 = f[(y0+1)*20 + x0], v11 = f[(y0+1)*20 + x0 + 1];
    float v = v00*(1.f-wy)*(1.f-wx) + v01*(1.f-wy)*wx + v10*wy*(1.f-wx) + v11*wy*wx;
    froiT[(size_t)c*(NI*NROIS) + (size_t)n*NROIS + r] = v;
}

// ---- FC2 heads: one warp per (row, output) ----
__global__ void __launch_bounds__(256)
fc2_warp(const float* __restrict__ h, const float* __restrict__ cfw,
         const float* __restrict__ cfb, const float* __restrict__ rfw,
         const float* __restrict__ rfb, float* __restrict__ out_cls,
         float* __restrict__ out_reg) {
    int w = (blockIdx.x*blockDim.x + threadIdx.x) >> 5;
    int lane = threadIdx.x & 31;
    if (w >= NI*NROIS*25) return;
    int m = w % 25;
    int row = w / 25;
    const float* hr = h + (size_t)row*1024;
    float s = 0.f;
    if (m < 21) {
        for (int k = lane; k < 1024; k += 32) s = fmaf(hr[k], cfw[k*21 + m], s);
    } else {
        int mm = m - 21;
        for (int k = lane; k < 1024; k += 32) s = fmaf(hr[k], rfw[k*4 + mm], s);
    }
    #pragma unroll
    for (int o = 16; o > 0; o >>= 1) s += __shfl_down_sync(0xFFFFFFFFu, s, o);
    if (lane == 0) {
        if (m < 21) out_cls[row*21 + m] = s + cfb[m];
        else        out_reg[row*4 + (m-21)] = s + rfb[m-21];
    }
}

extern "C" void kernel_launch(void* const* d_in, const int* in_sizes, int n_in,
                              void* d_out, int out_size) {
    const float* x      = (const float*)d_in[0];
    const float* w1     = (const float*)d_in[1];
    const float* b1     = (const float*)d_in[2];
    const float* w2     = (const float*)d_in[3];
    const float* b2     = (const float*)d_in[4];
    const float* w3     = (const float*)d_in[5];
    const float* b3     = (const float*)d_in[6];
    const float* w4     = (const float*)d_in[7];
    const float* b4     = (const float*)d_in[8];
    const float* cem_w4 = (const float*)d_in[9];
    const float* cem_b4 = (const float*)d_in[10];
    const float* cem_w5 = (const float*)d_in[11];
    const float* cem_b5 = (const float*)d_in[12];
    const float* cem_wg = (const float*)d_in[13];
    const float* cem_bg = (const float*)d_in[14];
    const float* rpn_dw = (const float*)d_in[15];
    const float* rpn_dwb= (const float*)d_in[16];
    const float* rpn_pw = (const float*)d_in[17];
    const float* rpn_pwb= (const float*)d_in[18];
    const float* cls_w  = (const float*)d_in[19];
    const float* cls_b  = (const float*)d_in[20];
    const float* reg_w  = (const float*)d_in[21];
    const float* reg_b  = (const float*)d_in[22];
    const float* sam_w  = (const float*)d_in[23];
    const float* sam_b  = (const float*)d_in[24];
    const float* fc_w   = (const float*)d_in[25];
    const float* fc_b   = (const float*)d_in[26];
    const float* cls_fw = (const float*)d_in[27];
    const float* cls_fb = (const float*)d_in[28];
    const float* reg_fw = (const float*)d_in[29];
    const float* reg_fb = (const float*)d_in[30];
    float* out = (float*)d_out;

    float* buf = nullptr;
    cudaGetSymbolAddress((void**)&buf, g_buf);
    unsigned long long* keys = nullptr;
    cudaGetSymbolAddress((void**)&keys, g_keys);

    cudaFuncSetAttribute(sort_kernel, cudaFuncAttributeMaxDynamicSharedMemorySize,
                         SORTN * (int)sizeof(unsigned long long));

    const int TB = 256;
    float* col = buf + O_COL;

    // ---- conv1: 3->24, 320->160 ----
    {
        int K = 27, N = 160*160, total = NI*K*N;
        im2col_kernel<<<CDIV(total, TB), TB>>>(x, col, 3, 320, 160, total);
        gemm_tiled<1,false><<<dim3(CDIV(N,64), CDIV(24,64), NI), 256>>>(
            w1, col, b1, buf+O_C1, 24, K, N, (long)K*N, (long)24*N, nullptr, nullptr);
    }
    maxpool3s2<<<CDIV(NI*24*80*80, TB), TB>>>(buf+O_C1, buf+O_P1, 24, 160, 80);
    // ---- conv2: 24->132, 80->40 ----
    {
        int K = 216, N = 40*40, total = NI*K*N;
        im2col_kernel<<<CDIV(total, TB), TB>>>(buf+O_P1, col, 24, 80, 40, total);
        gemm_tiled<1,false><<<dim3(CDIV(N,64), CDIV(132,64), NI), 256>>>(
            w2, col, b2, buf+O_C3, 132, K, N, (long)K*N, (long)132*N, nullptr, nullptr);
    }
    // ---- conv3: 132->264, 40->20 ----
    {
        int K = 1188, N = 400, total = NI*K*N;
        im2col_kernel<<<CDIV(total, TB), TB>>>(buf+O_C3, col, 132, 40, 20, total);
        gemm_tiled<1,false><<<dim3(CDIV(N,64), CDIV(264,64), NI), 256>>>(
            w3, col, b3, buf+O_C4, 264, K, N, (long)K*N, (long)264*N, nullptr, nullptr);
    }
    // ---- conv4: 264->528, 20->10 ----
    {
        int K = 2376, N = 100, total = NI*K*N;
        im2col_kernel<<<CDIV(total, TB), TB>>>(buf+O_C4, col, 264, 20, 10, total);
        gemm_tiled<1,false><<<dim3(CDIV(N,64), CDIV(528,64), NI), 256>>>(
            w4, col, b4, buf+O_C5, 528, K, N, (long)K*N, (long)528*N, nullptr, nullptr);
    }

    // ---- CEM ----
    gap_kernel<<<CDIV(NI*528, TB), TB>>>(buf+O_C5, buf+O_GLB);
    gfc_kernel<<<CDIV(NI*245, TB), TB>>>(buf+O_GLB, cem_wg, cem_bg, buf+O_GFC);
    gemm_tiled<0,false><<<dim3(CDIV(100,64), CDIV(245,64), NI), 256>>>(
        cem_w5, buf+O_C5, cem_b5, buf+O_CEM5, 245, 528, 100,
        (long)528*100, (long)245*100, nullptr, nullptr);
    gemm_tiled<3,false><<<dim3(CDIV(400,64), CDIV(245,64), NI), 256>>>(
        cem_w4, buf+O_C4, cem_b4, buf+O_FCEM, 245, 264, 400,
        (long)264*400, (long)245*400, buf+O_GFC, buf+O_CEM5);

    // ---- RPN ----
    dw5_kernel<<<CDIV(NI*245*400, TB), TB>>>(buf+O_FCEM, rpn_dw, rpn_dwb, buf+O_T);
    gemm_tiled<1,false><<<dim3(CDIV(400,64), CDIV(256,64), NI), 256>>>(
        rpn_pw, buf+O_T, rpn_pwb, buf+O_FRPN, 256, 245, 400,
        (long)245*400, (long)256*400, nullptr, nullptr);
    gemm_tiled<0,false><<<dim3(CDIV(400,64), CDIV(50,64), NI), 256>>>(
        cls_w, buf+O_FRPN, cls_b, buf+O_CLS, 50, 256, 400,
        (long)256*400, (long)50*400, nullptr, nullptr);
    gemm_tiled<0,false><<<dim3(CDIV(400,64), CDIV(100,64), NI), 256>>>(
        reg_w, buf+O_FRPN, reg_b, buf+O_REG, 100, 256, 400,
        (long)256*400, (long)100*400, nullptr, nullptr);
    gemm_tiled<2,false><<<dim3(CDIV(400,64), CDIV(245,64), NI), 256>>>(
        sam_w, buf+O_FRPN, sam_b, buf+O_FSAM, 245, 256, 400,
        (long)256*400, (long)245*400, buf+O_FCEM, nullptr);

    // ---- proposals ----
    scorebox_kernel<<<CDIV(NI*SORTN, TB), TB>>>(buf+O_CLS, buf+O_REG, buf+O_BOX, keys);
    sort_kernel<<<NI, 1024, SORTN*sizeof(unsigned long long)>>>(keys, buf+O_BOX, buf+O_BK);
    nms_kernel<<<NI, 256>>>(buf+O_BK, buf+O_ROI, out + (size_t)NI*NROIS*21 + (size_t)NI*NROIS*4);

    // ---- head ----
    psroi_kernel<<<CDIV(NI*NROIS*245, TB), TB>>>(buf+O_FSAM, buf+O_ROI, buf+O_FROI);
    // fc1: h[row][m] = relu(froiT^T @ fc_w + b): M=1024, K=245, N=1600, TRANSA, transposed store
    gemm_tiled<4,true><<<dim3(CDIV(NI*NROIS,64), CDIV(1024,64), 1), 256>>>(
        fc_w, buf+O_FROI, fc_b, buf+O_H, 1024, 245, NI*NROIS, 0, 0, nullptr, nullptr);
    fc2_warp<<<CDIV(NI*NROIS*25*32, TB), TB>>>(buf+O_H, cls_fw, cls_fb, reg_fw, reg_fb,
                                               out, out + (size_t)NI*NROIS*21);
}

// round 6
// speedup vs baseline: 2.6416x; 1.4858x over previous
#include <cuda_runtime.h>
#include <math.h>

#define CDIV(a,b) (((a)+(b)-1)/(b))

constexpr int NI     = 8;
constexpr int NANCH  = 10000;
constexpr int PRENMS = 1000;
constexpr int NROIS  = 200;

// ---- scratch layout (floats) ----
constexpr size_t O_C1  = 0;                constexpr size_t S_C1  = (size_t)NI*24*160*160;
constexpr size_t O_P1  = O_C1 + S_C1;      constexpr size_t S_P1  = (size_t)NI*24*80*80;
constexpr size_t O_C3  = O_P1 + S_P1;      constexpr size_t S_C3  = (size_t)NI*132*40*40;
constexpr size_t O_C4  = O_C3 + S_C3;      constexpr size_t S_C4  = (size_t)NI*264*20*20;
constexpr size_t O_C5  = O_C4 + S_C4;      constexpr size_t S_C5  = (size_t)NI*528*10*10;
constexpr size_t O_GLB = O_C5 + S_C5;      constexpr size_t S_GLB = (size_t)NI*528;
constexpr size_t O_GFC = O_GLB + S_GLB;    constexpr size_t S_GFC = (size_t)NI*245;
constexpr size_t O_CEM5= O_GFC + S_GFC;    constexpr size_t S_CEM5= (size_t)NI*245*100;
constexpr size_t O_FCEM= O_CEM5 + S_CEM5;  constexpr size_t S_FCEM= (size_t)NI*245*400;
constexpr size_t O_T   = O_FCEM + S_FCEM;  constexpr size_t S_T   = S_FCEM;
constexpr size_t O_FRPN= O_T + S_T;        constexpr size_t S_FRPN= (size_t)NI*256*400;
constexpr size_t O_CLS = O_FRPN + S_FRPN;  constexpr size_t S_CLS = (size_t)NI*50*400;
constexpr size_t O_REG = O_CLS + S_CLS;    constexpr size_t S_REG = (size_t)NI*100*400;
constexpr size_t O_FSAM= O_REG + S_REG;    constexpr size_t S_FSAM= S_FCEM;
constexpr size_t O_BOX = O_FSAM + S_FSAM;  constexpr size_t S_BOX = (size_t)NI*NANCH*4;
constexpr size_t O_BK  = O_BOX + S_BOX;    constexpr size_t S_BK  = (size_t)NI*PRENMS*4;
constexpr size_t O_ROI = O_BK + S_BK;      constexpr size_t S_ROI = (size_t)NI*NROIS*4;
constexpr size_t O_FROI= O_ROI + S_ROI;    constexpr size_t S_FROI= (size_t)245*NI*NROIS; // transposed [245][1600]
constexpr size_t O_H   = O_FROI + S_FROI;  constexpr size_t S_H   = (size_t)NI*NROIS*1024;
constexpr size_t O_COL = O_H + S_H;        constexpr size_t S_COL = (size_t)NI*27*160*160; // max im2col (conv1)
constexpr size_t TOTAL = O_COL + S_COL;

__device__ float g_buf[TOTAL];
__device__ unsigned long long g_keys[(size_t)NI*NANCH];
__device__ unsigned int g_mask[(size_t)NI*1024*32];   // suppression bitmask [n][i][jword]

// =================== im2col for 3x3 stride-2 SAME conv ===================
__global__ void im2col_kernel(const float* __restrict__ in, float* __restrict__ out,
                              int Cin, int Hin, int Hout, int total) {
    int idx = blockIdx.x*blockDim.x + threadIdx.x;
    if (idx >= total) return;
    int P = Hout*Hout;
    int p = idx % P;
    int k = (idx / P) % (Cin*9);
    int n = idx / (P*Cin*9);
    int ic = k / 9, r = k % 9;
    int ky = r / 3, kx = r % 3;
    int oy = p / Hout, ox = p % Hout;
    int iy = 2*oy + ky, ix = 2*ox + kx;
    float v = 0.f;
    if (iy < Hin && ix < Hin)
        v = in[(((size_t)n*Cin + ic)*Hin + iy)*Hin + ix];
    out[idx] = v;
}

// =================== unified tiled GEMM ===================
// MODE: 0 bias, 1 bias+relu, 2 fsam: e1*sigmoid(s), 3 fcem adds, 4 relu + transposed store C[n][m]
template<int MODE, bool TRANSA>
__global__ void __launch_bounds__(256)
gemm_tiled(const float* __restrict__ A, const float* __restrict__ B,
           const float* __restrict__ bias, float* __restrict__ C,
           int M, int K, int N, long sB, long sC,
           const float* __restrict__ e1, const float* __restrict__ e2) {
    __shared__ float As[16][68];
    __shared__ float Bs[16][68];
    int nimg = blockIdx.z;
    int m0 = blockIdx.y*64, n0 = blockIdx.x*64;
    const float* Bp = B + (long)nimg*sB;
    float* Cp = C + (long)nimg*sC;
    int tid = threadIdx.x;
    int tx = tid % 16, ty = tid / 16;
    float acc[4][4] = {};
    for (int k0 = 0; k0 < K; k0 += 16) {
        if (!TRANSA) {
            int r = tid >> 2, c = (tid & 3) * 4;
            #pragma unroll
            for (int i = 0; i < 4; i++) {
                int mm = m0 + r, kk = k0 + c + i;
                As[c+i][r] = (mm < M && kk < K) ? A[(long)mm*K + kk] : 0.f;
            }
        } else {
            int r = tid >> 4, c = (tid & 15) * 4;
            #pragma unroll
            for (int i = 0; i < 4; i++) {
                int kk = k0 + r, mm = m0 + c + i;
                As[r][c+i] = (mm < M && kk < K) ? A[(long)kk*M + mm] : 0.f;
            }
        }
        {
            int r = tid >> 4, c = (tid & 15) * 4;
            #pragma unroll
            for (int i = 0; i < 4; i++) {
                int kk = k0 + r, nn = n0 + c + i;
                Bs[r][c+i] = (kk < K && nn < N) ? Bp[(long)kk*N + nn] : 0.f;
            }
        }
        __syncthreads();
        #pragma unroll
        for (int kk = 0; kk < 16; kk++) {
            float4 av = *reinterpret_cast<const float4*>(&As[kk][ty*4]);
            float4 bv = *reinterpret_cast<const float4*>(&Bs[kk][tx*4]);
            float a[4] = {av.x, av.y, av.z, av.w};
            float b[4] = {bv.x, bv.y, bv.z, bv.w};
            #pragma unroll
            for (int i = 0; i < 4; i++)
                #pragma unroll
                for (int j = 0; j < 4; j++)
                    acc[i][j] = fmaf(a[i], b[j], acc[i][j]);
        }
        __syncthreads();
    }
    #pragma unroll
    for (int i = 0; i < 4; i++) {
        int m = m0 + ty*4 + i;
        if (m >= M) continue;
        float bv = bias[m];
        #pragma unroll
        for (int j = 0; j < 4; j++) {
            int n = n0 + tx*4 + j;
            if (n >= N) continue;
            float s = acc[i][j] + bv;
            if (MODE == 1) s = fmaxf(s, 0.f);
            else if (MODE == 2) {
                s = e1[(long)nimg*sC + (long)m*N + n] * (1.f/(1.f + expf(-s)));
            } else if (MODE == 3) {
                int y = n / 20, x = n % 20;
                s += e1[nimg*245 + m] + e2[((long)nimg*245 + m)*100 + (y/2)*10 + (x/2)];
            }
            if (MODE == 4) {
                s = fmaxf(s, 0.f);
                Cp[(long)n*M + m] = s;
            } else {
                Cp[(long)m*N + n] = s;
            }
        }
    }
}

// =================== 3x3 stride-2 maxpool SAME ===================
__global__ void maxpool3s2(const float* __restrict__ in, float* __restrict__ out,
                           int C, int Hin, int Hout) {
    int t = blockIdx.x*blockDim.x + threadIdx.x;
    int total = NI*C*Hout*Hout;
    if (t >= total) return;
    int ox = t % Hout;
    int oy = (t / Hout) % Hout;
    int nc = t / (Hout*Hout);
    const float* ip = in + (size_t)nc*Hin*Hin;
    float m = -INFINITY;
    #pragma unroll
    for (int ky = 0; ky < 3; ky++) {
        int iy = 2*oy + ky;
        if (iy >= Hin) continue;
        #pragma unroll
        for (int kx = 0; kx < 3; kx++) {
            int ix = 2*ox + kx;
            if (ix >= Hin) continue;
            m = fmaxf(m, ip[iy*Hin+ix]);
        }
    }
    out[t] = m;
}

__global__ void gap_kernel(const float* __restrict__ c5, float* __restrict__ glb) {
    int t = blockIdx.x*blockDim.x + threadIdx.x;
    if (t >= NI*528) return;
    const float* p = c5 + (size_t)t*100;
    float s = 0.f;
    for (int i = 0; i < 100; i++) s += p[i];
    glb[t] = s / 100.f;
}

__global__ void gfc_kernel(const float* __restrict__ glb, const float* __restrict__ wg,
                           const float* __restrict__ bg, float* __restrict__ gfc) {
    int t = blockIdx.x*blockDim.x + threadIdx.x;
    if (t >= NI*245) return;
    int k = t % 245, n = t / 245;
    float s = bg[k];
    const float* g = glb + n*528;
    for (int c = 0; c < 528; c++) s += g[c] * wg[c*245 + k];
    gfc[t] = s;
}

// ---- depthwise 5x5 SAME + relu ----
__global__ void dw5_kernel(const float* __restrict__ in, const float* __restrict__ w,
                           const float* __restrict__ bias, float* __restrict__ out) {
    int t = blockIdx.x*blockDim.x + threadIdx.x;
    int total = NI*245*400;
    if (t >= total) return;
    int p = t % 400;
    int k = (t / 400) % 245;
    int y = p / 20, x = p % 20;
    const float* ip = in + (size_t)(t/400)*400;
    const float* wk = w + k*25;
    float s = bias[k];
    #pragma unroll
    for (int ky = 0; ky < 5; ky++) {
        int iy = y - 2 + ky;
        if (iy < 0 || iy >= 20) continue;
        #pragma unroll
        for (int kx = 0; kx < 5; kx++) {
            int ix = x - 2 + kx;
            if (ix < 0 || ix >= 20) continue;
            s += ip[iy*20+ix] * wk[ky*5+kx];
        }
    }
    out[t] = fmaxf(s, 0.f);
}

// ---- scores + decoded boxes + sort keys ----
__global__ void scorebox_kernel(const float* __restrict__ clsmap, const float* __restrict__ regmap,
                                float* __restrict__ boxes, unsigned long long* __restrict__ keys) {
    int t = blockIdx.x*blockDim.x + threadIdx.x;
    if (t >= NI*NANCH) return;
    int i = t % NANCH;
    int n = t / NANCH;
    int a = i % 25;
    int x = (i / 25) % 20;
    int y = i / 500;
    int p = y*20 + x;
    const float* cm = clsmap + (size_t)n*50*400;
    float c0 = cm[(a*2  )*400 + p];
    float c1 = cm[(a*2+1)*400 + p];
    float score = 1.f / (1.f + expf(c0 - c1));
    const float* rm = regmap + (size_t)n*100*400;
    float d0 = rm[(a*4  )*400 + p];
    float d1 = rm[(a*4+1)*400 + p];
    float d2 = rm[(a*4+2)*400 + p];
    float d3 = rm[(a*4+3)*400 + p];
    const float scales[5] = {32.f, 64.f, 128.f, 256.f, 512.f};
    const float ratios[5] = {0.5f, 0.75f, 1.0f, 4.0f/3.0f, 2.0f};
    int si = a / 5, ri = a % 5;
    float sq = sqrtf(ratios[ri]);
    float aw = scales[si] / sq;
    float ah = scales[si] * sq;
    float acx = (x + 0.5f) * 16.f;
    float acy = (y + 0.5f) * 16.f;
    float cx = d0*aw + acx;
    float cy = d1*ah + acy;
    float w  = expf(d2) * aw;
    float h  = expf(d3) * ah;
    float* b = boxes + ((size_t)n*NANCH + i)*4;
    b[0] = fminf(fmaxf(cx - 0.5f*w, 0.f), 319.f);
    b[1] = fminf(fmaxf(cy - 0.5f*h, 0.f), 319.f);
    b[2] = fminf(fmaxf(cx + 0.5f*w, 0.f), 319.f);
    b[3] = fminf(fmaxf(cy + 0.5f*h, 0.f), 319.f);
    unsigned sb = __float_as_uint(score);  // score > 0 -> bit-monotone
    keys[t] = ((unsigned long long)sb << 32) | (unsigned long long)(0xFFFFFFFFu - (unsigned)i);
}

// ---- exact top-1000 per image: 64-bit radix select + bitonic sort of 1024 ----
__global__ void __launch_bounds__(1024)
topk_kernel(const unsigned long long* __restrict__ keys,
            const float* __restrict__ boxes, float* __restrict__ bk) {
    __shared__ unsigned int hist[256];
    __shared__ unsigned long long sh_prefix;
    __shared__ int sh_need;
    __shared__ unsigned int sh_cnt;
    __shared__ unsigned long long sk[1024];
    int n = blockIdx.x;
    int tid = threadIdx.x;
    const unsigned long long* kp = keys + (size_t)n*NANCH;

    if (tid == 0) { sh_prefix = 0ull; sh_need = PRENMS; sh_cnt = 0u; }
    __syncthreads();

    // 8-round radix select (MSD first) -> exact 1000th-largest key
    for (int shift = 56; shift >= 0; shift -= 8) {
        if (tid < 256) hist[tid] = 0u;
        __syncthreads();
        unsigned long long prefmask = (shift == 56) ? 0ull : (~0ull << (shift + 8));
        unsigned long long pref = sh_prefix;
        for (int i = tid; i < NANCH; i += 1024) {
            unsigned long long k = kp[i];
            if ((k & prefmask) == pref)
                atomicAdd(&hist[(unsigned)(k >> shift) & 255u], 1u);
        }
        __syncthreads();
        if (tid == 0) {
            int need = sh_need;
            unsigned cum = 0;
            int d = 255;
            for (; d >= 0; d--) { cum += hist[d]; if ((int)cum >= need) break; }
            sh_need = need - (int)(cum - hist[d]);
            sh_prefix = pref | ((unsigned long long)d << shift);
        }
        __syncthreads();
    }
    unsigned long long T = sh_prefix;

    // compact keys >= T (exactly 1000, keys unique), pad to 1024 with 0
    if (tid < 24) sk[1000 + tid] = 0ull;
    for (int i = tid; i < NANCH; i += 1024) {
        unsigned long long k = kp[i];
        if (k >= T) sk[atomicAdd(&sh_cnt, 1u)] = k;
    }
    __syncthreads();

    // bitonic sort 1024 descending
    for (int size = 2; size <= 1024; size <<= 1) {
        for (int stride = size >> 1; stride > 0; stride >>= 1) {
            if (tid < 512) {
                int lo = ((tid & ~(stride-1)) << 1) | (tid & (stride-1));
                int hi = lo + stride;
                unsigned long long a = sk[lo], c = sk[hi];
                bool desc = ((lo & size) == 0);
                if (desc ? (a < c) : (a > c)) { sk[lo] = c; sk[hi] = a; }
            }
            __syncthreads();
        }
    }

    // gather top-1000 boxes
    if (tid < PRENMS) {
        unsigned idx = 0xFFFFFFFFu - (unsigned)(sk[tid] & 0xFFFFFFFFull);
        const float* src = boxes + ((size_t)n*NANCH + idx)*4;
        float* dst = bk + ((size_t)n*PRENMS + tid)*4;
        dst[0] = src[0]; dst[1] = src[1]; dst[2] = src[2]; dst[3] = src[3];
    }
}

// ---- suppression bitmask: mask[n][i][w] bit b = (j=w*32+b > i) && IoU>0.7 ----
__global__ void __launch_bounds__(256)
nms_mask_kernel(const float* __restrict__ bk, unsigned int* __restrict__ mask) {
    __shared__ float4 box[PRENMS];
    __shared__ float  area[PRENMS];
    int n = blockIdx.x;
    int i0 = blockIdx.y * 8;
    int tid = threadIdx.x;
    const float* b = bk + (size_t)n*PRENMS*4;
    for (int i = tid; i < PRENMS; i += 256) {
        float x1 = b[i*4], y1 = b[i*4+1], x2 = b[i*4+2], y2 = b[i*4+3];
        box[i] = make_float4(x1, y1, x2, y2);
        area[i] = (x2-x1)*(y2-y1);
    }
    __syncthreads();
    int w  = tid & 31;
    int il = tid >> 5;
    int i = i0 + il;
    if (i >= PRENMS) return;
    float4 bi = box[i];
    float ai = area[i];
    unsigned m = 0u;
    int jbase = w * 32;
    #pragma unroll 4
    for (int bbit = 0; bbit < 32; bbit++) {
        int j = jbase + bbit;
        if (j > i && j < PRENMS) {
            float ix1 = fmaxf(bi.x, box[j].x);
            float iy1 = fmaxf(bi.y, box[j].y);
            float ix2 = fminf(bi.z, box[j].z);
            float iy2 = fminf(bi.w, box[j].w);
            float inter = fmaxf(ix2-ix1, 0.f) * fmaxf(iy2-iy1, 0.f);
            float iou = inter / (ai + area[j] - inter + 1e-9f);
            if (iou > 0.7f) m |= (1u << bbit);
        }
    }
    mask[((size_t)n*1024 + i)*32 + w] = m;
}

// ---- single-warp NMS scan + stable partition -> 200 rois ----
__global__ void __launch_bounds__(32)
nms_scan_kernel(const unsigned int* __restrict__ mask, const float* __restrict__ bk,
                float* __restrict__ rois, float* __restrict__ out_rois) {
    __shared__ unsigned char keep[PRENMS];
    __shared__ int order[NROIS];
    int n = blockIdx.x;
    int lane = threadIdx.x;
    const unsigned int* mp = mask + (size_t)n*1024*32;
    unsigned removed = 0u;   // lane owns j-bits [lane*32, lane*32+32)
    unsigned next_m = mp[0*32 + lane];
    for (int i = 0; i < PRENMS; i++) {
        unsigned m = next_m;
        if (i + 1 < PRENMS) next_m = mp[(i+1)*32 + lane];
        unsigned rw = __shfl_sync(0xFFFFFFFFu, removed, i >> 5);
        bool keep_i = ((rw >> (i & 31)) & 1u) == 0u;
        if (keep_i) removed |= m;
        if (lane == 0) keep[i] = keep_i ? 1 : 0;
    }
    __syncwarp();
    if (lane == 0) {
        int c = 0;
        for (int i = 0; i < PRENMS && c < NROIS; i++) if (keep[i])  order[c++] = i;
        for (int i = 0; i < PRENMS && c < NROIS; i++) if (!keep[i]) order[c++] = i;
    }
    __syncwarp();
    const float* b = bk + (size_t)n*PRENMS*4;
    for (int r = lane; r < NROIS; r += 32) {
        int idx = order[r];
        float x1 = b[idx*4], y1 = b[idx*4+1], x2 = b[idx*4+2], y2 = b[idx*4+3];
        float* dst = rois + ((size_t)n*NROIS + r)*4;
        dst[0] = x1; dst[1] = y1; dst[2] = x2; dst[3] = y2;
        float* o = out_rois + ((size_t)n*NROIS + r)*4;
        o[0] = x1; o[1] = y1; o[2] = x2; o[3] = y2;
    }
}

// ---- PSRoI pooling: stores TRANSPOSED froiT[c][n*200+r] for fc1 GEMM ----
__global__ void psroi_kernel(const float* __restrict__ fsam, const float* __restrict__ rois,
                             float* __restrict__ froiT) {
    int t = blockIdx.x*blockDim.x + threadIdx.x;
    int total = NI*NROIS*245;
    if (t >= total) return;
    int c = t % 245;
    int r = (t / 245) % NROIS;
    int n = t / (245*NROIS);
    const float* ro = rois + ((size_t)n*NROIS + r)*4;
    float x1 = ro[0] * (1.f/16.f), y1 = ro[1] * (1.f/16.f);
    float x2 = ro[2] * (1.f/16.f), y2 = ro[3] * (1.f/16.f);
    float bw = fmaxf(x2-x1, 0.1f) * (1.f/7.f);
    float bh = fmaxf(y2-y1, 0.1f) * (1.f/7.f);
    int ij = c % 49;
    int i = ij / 7, j = ij % 7;
    float sx = x1 + (j + 0.5f) * bw;
    float sy = y1 + (i + 0.5f) * bh;
    float x = fminf(fmaxf(sx, 0.f), 19.f);
    float y = fminf(fmaxf(sy, 0.f), 19.f);
    int y0 = min(max((int)floorf(y), 0), 18);
    int x0 = min(max((int)floorf(x), 0), 18);
    float wy = y - (float)y0;
    float wx = x - (float)x0;
    const float* f = fsam + ((size_t)n*245 + c)*400;
    float v00 = f[y0*20 + x0],     v01 = f[y0*20 + x0 + 1];
    float v10 = f[(y0+1)*20 + x0], v11 = f[(y0+1)*20 + x0 + 1];
    float v = v00*(1.f-wy)*(1.f-wx) + v01*(1.f-wy)*wx + v10*wy*(1.f-wx) + v11*wy*wx;
    froiT[(size_t)c*(NI*NROIS) + (size_t)n*NROIS + r] = v;
}

// ---- FC2 heads: one warp per (row, output) ----
__global__ void __launch_bounds__(256)
fc2_warp(const float* __restrict__ h, const float* __restrict__ cfw,
         const float* __restrict__ cfb, const float* __restrict__ rfw,
         const float* __restrict__ rfb, float* __restrict__ out_cls,
         float* __restrict__ out_reg) {
    int w = (blockIdx.x*blockDim.x + threadIdx.x) >> 5;
    int lane = threadIdx.x & 31;
    if (w >= NI*NROIS*25) return;
    int m = w % 25;
    int row = w / 25;
    const float* hr = h + (size_t)row*1024;
    float s = 0.f;
    if (m < 21) {
        for (int k = lane; k < 1024; k += 32) s = fmaf(hr[k], cfw[k*21 + m], s);
    } else {
        int mm = m - 21;
        for (int k = lane; k < 1024; k += 32) s = fmaf(hr[k], rfw[k*4 + mm], s);
    }
    #pragma unroll
    for (int o = 16; o > 0; o >>= 1) s += __shfl_down_sync(0xFFFFFFFFu, s, o);
    if (lane == 0) {
        if (m < 21) out_cls[row*21 + m] = s + cfb[m];
        else        out_reg[row*4 + (m-21)] = s + rfb[m-21];
    }
}

extern "C" void kernel_launch(void* const* d_in, const int* in_sizes, int n_in,
                              void* d_out, int out_size) {
    const float* x      = (const float*)d_in[0];
    const float* w1     = (const float*)d_in[1];
    const float* b1     = (const float*)d_in[2];
    const float* w2     = (const float*)d_in[3];
    const float* b2     = (const float*)d_in[4];
    const float* w3     = (const float*)d_in[5];
    const float* b3     = (const float*)d_in[6];
    const float* w4     = (const float*)d_in[7];
    const float* b4     = (const float*)d_in[8];
    const float* cem_w4 = (const float*)d_in[9];
    const float* cem_b4 = (const float*)d_in[10];
    const float* cem_w5 = (const float*)d_in[11];
    const float* cem_b5 = (const float*)d_in[12];
    const float* cem_wg = (const float*)d_in[13];
    const float* cem_bg = (const float*)d_in[14];
    const float* rpn_dw = (const float*)d_in[15];
    const float* rpn_dwb= (const float*)d_in[16];
    const float* rpn_pw = (const float*)d_in[17];
    const float* rpn_pwb= (const float*)d_in[18];
    const float* cls_w  = (const float*)d_in[19];
    const float* cls_b  = (const float*)d_in[20];
    const float* reg_w  = (const float*)d_in[21];
    const float* reg_b  = (const float*)d_in[22];
    const float* sam_w  = (const float*)d_in[23];
    const float* sam_b  = (const float*)d_in[24];
    const float* fc_w   = (const float*)d_in[25];
    const float* fc_b   = (const float*)d_in[26];
    const float* cls_fw = (const float*)d_in[27];
    const float* cls_fb = (const float*)d_in[28];
    const float* reg_fw = (const float*)d_in[29];
    const float* reg_fb = (const float*)d_in[30];
    float* out = (float*)d_out;

    float* buf = nullptr;
    cudaGetSymbolAddress((void**)&buf, g_buf);
    unsigned long long* keys = nullptr;
    cudaGetSymbolAddress((void**)&keys, g_keys);
    unsigned int* mask = nullptr;
    cudaGetSymbolAddress((void**)&mask, g_mask);

    const int TB = 256;
    float* col = buf + O_COL;

    // ---- conv1: 3->24, 320->160 ----
    {
        int K = 27, N = 160*160, total = NI*K*N;
        im2col_kernel<<<CDIV(total, TB), TB>>>(x, col, 3, 320, 160, total);
        gemm_tiled<1,false><<<dim3(CDIV(N,64), CDIV(24,64), NI), 256>>>(
            w1, col, b1, buf+O_C1, 24, K, N, (long)K*N, (long)24*N, nullptr, nullptr);
    }
    maxpool3s2<<<CDIV(NI*24*80*80, TB), TB>>>(buf+O_C1, buf+O_P1, 24, 160, 80);
    // ---- conv2: 24->132, 80->40 ----
    {
        int K = 216, N = 40*40, total = NI*K*N;
        im2col_kernel<<<CDIV(total, TB), TB>>>(buf+O_P1, col, 24, 80, 40, total);
        gemm_tiled<1,false><<<dim3(CDIV(N,64), CDIV(132,64), NI), 256>>>(
            w2, col, b2, buf+O_C3, 132, K, N, (long)K*N, (long)132*N, nullptr, nullptr);
    }
    // ---- conv3: 132->264, 40->20 ----
    {
        int K = 1188, N = 400, total = NI*K*N;
        im2col_kernel<<<CDIV(total, TB), TB>>>(buf+O_C3, col, 132, 40, 20, total);
        gemm_tiled<1,false><<<dim3(CDIV(N,64), CDIV(264,64), NI), 256>>>(
            w3, col, b3, buf+O_C4, 264, K, N, (long)K*N, (long)264*N, nullptr, nullptr);
    }
    // ---- conv4: 264->528, 20->10 ----
    {
        int K = 2376, N = 100, total = NI*K*N;
        im2col_kernel<<<CDIV(total, TB), TB>>>(buf+O_C4, col, 264, 20, 10, total);
        gemm_tiled<1,false><<<dim3(CDIV(N,64), CDIV(528,64), NI), 256>>>(
            w4, col, b4, buf+O_C5, 528, K, N, (long)K*N, (long)528*N, nullptr, nullptr);
    }

    // ---- CEM ----
    gap_kernel<<<CDIV(NI*528, TB), TB>>>(buf+O_C5, buf+O_GLB);
    gfc_kernel<<<CDIV(NI*245, TB), TB>>>(buf+O_GLB, cem_wg, cem_bg, buf+O_GFC);
    gemm_tiled<0,false><<<dim3(CDIV(100,64), CDIV(245,64), NI), 256>>>(
        cem_w5, buf+O_C5, cem_b5, buf+O_CEM5, 245, 528, 100,
        (long)528*100, (long)245*100, nullptr, nullptr);
    gemm_tiled<3,false><<<dim3(CDIV(400,64), CDIV(245,64), NI), 256>>>(
        cem_w4, buf+O_C4, cem_b4, buf+O_FCEM, 245, 264, 400,
        (long)264*400, (long)245*400, buf+O_GFC, buf+O_CEM5);

    // ---- RPN ----
    dw5_kernel<<<CDIV(NI*245*400, TB), TB>>>(buf+O_FCEM, rpn_dw, rpn_dwb, buf+O_T);
    gemm_tiled<1,false><<<dim3(CDIV(400,64), CDIV(256,64), NI), 256>>>(
        rpn_pw, buf+O_T, rpn_pwb, buf+O_FRPN, 256, 245, 400,
        (long)245*400, (long)256*400, nullptr, nullptr);
    gemm_tiled<0,false><<<dim3(CDIV(400,64), CDIV(50,64), NI), 256>>>(
        cls_w, buf+O_FRPN, cls_b, buf+O_CLS, 50, 256, 400,
        (long)256*400, (long)50*400, nullptr, nullptr);
    gemm_tiled<0,false><<<dim3(CDIV(400,64), CDIV(100,64), NI), 256>>>(
        reg_w, buf+O_FRPN, reg_b, buf+O_REG, 100, 256, 400,
        (long)256*400, (long)100*400, nullptr, nullptr);
    gemm_tiled<2,false><<<dim3(CDIV(400,64), CDIV(245,64), NI), 256>>>(
        sam_w, buf+O_FRPN, sam_b, buf+O_FSAM, 245, 256, 400,
        (long)256*400, (long)245*400, buf+O_FCEM, nullptr);

    // ---- proposals ----
    scorebox_kernel<<<CDIV(NI*NANCH, TB), TB>>>(buf+O_CLS, buf+O_REG, buf+O_BOX, keys);
    topk_kernel<<<NI, 1024>>>(keys, buf+O_BOX, buf+O_BK);
    nms_mask_kernel<<<dim3(NI, 125), 256>>>(buf+O_BK, mask);
    nms_scan_kernel<<<NI, 32>>>(mask, buf+O_BK, buf+O_ROI,
                                out + (size_t)NI*NROIS*21 + (size_t)NI*NROIS*4);

    // ---- head ----
    psroi_kernel<<<CDIV(NI*NROIS*245, TB), TB>>>(buf+O_FSAM, buf+O_ROI, buf+O_FROI);
    gemm_tiled<4,true><<<dim3(CDIV(NI*NROIS,64), CDIV(1024,64), 1), 256>>>(
        fc_w, buf+O_FROI, fc_b, buf+O_H, 1024, 245, NI*NROIS, 0, 0, nullptr, nullptr);
    fc2_warp<<<CDIV(NI*NROIS*25*32, TB), TB>>>(buf+O_H, cls_fw, cls_fb, reg_fw, reg_fb,
                                               out, out + (size_t)NI*NROIS*21);
}

// round 7
// speedup vs baseline: 2.9335x; 1.1105x over previous
#include <cuda_runtime.h>
#include <math.h>

#define CDIV(a,b) (((a)+(b)-1)/(b))

constexpr int NI     = 8;
constexpr int NANCH  = 10000;
constexpr int PRENMS = 1000;
constexpr int NROIS  = 200;

// ---- scratch layout (floats) ----
constexpr size_t O_C1  = 0;                constexpr size_t S_C1  = (size_t)NI*24*160*160;
constexpr size_t O_P1  = O_C1 + S_C1;      constexpr size_t S_P1  = (size_t)NI*24*80*80;
constexpr size_t O_C3  = O_P1 + S_P1;      constexpr size_t S_C3  = (size_t)NI*132*40*40;
constexpr size_t O_C4  = O_C3 + S_C3;      constexpr size_t S_C4  = (size_t)NI*264*20*20;
constexpr size_t O_C5  = O_C4 + S_C4;      constexpr size_t S_C5  = (size_t)NI*528*10*10;
constexpr size_t O_GLB = O_C5 + S_C5;      constexpr size_t S_GLB = (size_t)NI*528;
constexpr size_t O_GFC = O_GLB + S_GLB;    constexpr size_t S_GFC = (size_t)NI*245;
constexpr size_t O_CEM5= O_GFC + S_GFC;    constexpr size_t S_CEM5= (size_t)NI*245*100;
constexpr size_t O_FCEM= O_CEM5 + S_CEM5;  constexpr size_t S_FCEM= (size_t)NI*245*400;
constexpr size_t O_T   = O_FCEM + S_FCEM;  constexpr size_t S_T   = S_FCEM;
constexpr size_t O_FRPN= O_T + S_T;        constexpr size_t S_FRPN= (size_t)NI*256*400;
constexpr size_t O_CLS = O_FRPN + S_FRPN;  constexpr size_t S_CLS = (size_t)NI*50*400;
constexpr size_t O_REG = O_CLS + S_CLS;    constexpr size_t S_REG = (size_t)NI*100*400;
constexpr size_t O_FSAM= O_REG + S_REG;    constexpr size_t S_FSAM= S_FCEM;
constexpr size_t O_BOX = O_FSAM + S_FSAM;  constexpr size_t S_BOX = (size_t)NI*NANCH*4;
constexpr size_t O_BK  = O_BOX + S_BOX;    constexpr size_t S_BK  = (size_t)NI*PRENMS*4;
constexpr size_t O_ROI = O_BK + S_BK;      constexpr size_t S_ROI = (size_t)NI*NROIS*4;
constexpr size_t O_FROI= O_ROI + S_ROI;    constexpr size_t S_FROI= (size_t)245*NI*NROIS; // transposed [245][1600]
constexpr size_t O_H   = O_FROI + S_FROI;  constexpr size_t S_H   = (size_t)NI*NROIS*1024;
constexpr size_t O_PART= O_H + S_H;        constexpr size_t S_PART= (size_t)4*NI*264*400; // split-K partials (max: conv3)
constexpr size_t TOTAL = O_PART + S_PART;

__device__ float g_buf[TOTAL];
__device__ unsigned long long g_keys[(size_t)NI*NANCH];
__device__ unsigned int g_mask[(size_t)NI*1024*32];   // suppression bitmask [n][i][jword]

// =================== unified tiled GEMM (optionally implicit-conv B, optionally split-K) ==========
// C[m][n] = sum_k A[m][k]*B[k][n]. 64x64 tile, 256 thr, 4x4/thread.
// MODE: 0 bias, 1 bias+relu, 2 fsam: e1*sigmoid(s), 3 fcem adds, 4 relu + transposed store C[n][m],
//       5 raw partial store (split-K; no bias)
// CONV: B[k][n] is im2col of 3x3 stride-2 SAME conv input (decoded at load time)
template<int MODE, bool TRANSA, bool CONV>
__global__ void __launch_bounds__(256)
gemm_tiled(const float* __restrict__ A, const float* __restrict__ B,
           const float* __restrict__ bias, float* __restrict__ C,
           int M, int K, int N, long sB, long sC,
           const float* __restrict__ e1, const float* __restrict__ e2,
           int Cin, int Hin, int Hout, int S, int kLen) {
    __shared__ float As[16][68];
    __shared__ float Bs[16][68];
    int nimg, spl;
    if (MODE == 5) { nimg = blockIdx.z / S; spl = blockIdx.z % S; }
    else           { nimg = blockIdx.z;     spl = 0; }
    int kStart = spl * kLen;
    int kEnd   = min(K, kStart + kLen);
    int m0 = blockIdx.y*64, n0 = blockIdx.x*64;
    const float* Bp = B + (long)nimg*sB;
    float* Cp = (MODE == 5) ? C + ((long)spl*NI + nimg)*M*N
                            : C + (long)nimg*sC;
    int tid = threadIdx.x;
    int tx = tid % 16, ty = tid / 16;
    float acc[4][4] = {};
    for (int k0 = kStart; k0 < kEnd; k0 += 16) {
        if (!TRANSA) {
            int r = tid >> 2, c = (tid & 3) * 4;
            #pragma unroll
            for (int i = 0; i < 4; i++) {
                int mm = m0 + r, kk = k0 + c + i;
                As[c+i][r] = (mm < M && kk < kEnd) ? A[(long)mm*K + kk] : 0.f;
            }
        } else {
            int r = tid >> 4, c = (tid & 15) * 4;
            #pragma unroll
            for (int i = 0; i < 4; i++) {
                int kk = k0 + r, mm = m0 + c + i;
                As[r][c+i] = (mm < M && kk < kEnd) ? A[(long)kk*M + mm] : 0.f;
            }
        }
        if (CONV) {
            int r = tid >> 4, c = (tid & 15) * 4;
            int kk = k0 + r;
            bool kv = kk < kEnd;
            int ic = 0, ky = 0, kx = 0;
            if (kv) { ic = kk / 9; int rem = kk - ic*9; ky = rem / 3; kx = rem - ky*3; }
            #pragma unroll
            for (int i = 0; i < 4; i++) {
                int nn = n0 + c + i;
                float v = 0.f;
                if (kv && nn < N) {
                    int oy = nn / Hout, ox = nn - oy*Hout;
                    int iy = 2*oy + ky, ix = 2*ox + kx;
                    if (iy < Hin && ix < Hin)
                        v = Bp[((long)ic*Hin + iy)*Hin + ix];
                }
                Bs[r][c+i] = v;
            }
        } else {
            int r = tid >> 4, c = (tid & 15) * 4;
            #pragma unroll
            for (int i = 0; i < 4; i++) {
                int kk = k0 + r, nn = n0 + c + i;
                Bs[r][c+i] = (kk < kEnd && nn < N) ? Bp[(long)kk*N + nn] : 0.f;
            }
        }
        __syncthreads();
        #pragma unroll
        for (int kk = 0; kk < 16; kk++) {
            float4 av = *reinterpret_cast<const float4*>(&As[kk][ty*4]);
            float4 bv = *reinterpret_cast<const float4*>(&Bs[kk][tx*4]);
            float a[4] = {av.x, av.y, av.z, av.w};
            float b[4] = {bv.x, bv.y, bv.z, bv.w};
            #pragma unroll
            for (int i = 0; i < 4; i++)
                #pragma unroll
                for (int j = 0; j < 4; j++)
                    acc[i][j] = fmaf(a[i], b[j], acc[i][j]);
        }
        __syncthreads();
    }
    #pragma unroll
    for (int i = 0; i < 4; i++) {
        int m = m0 + ty*4 + i;
        if (m >= M) continue;
        float bv = (MODE == 5) ? 0.f : bias[m];
        #pragma unroll
        for (int j = 0; j < 4; j++) {
            int n = n0 + tx*4 + j;
            if (n >= N) continue;
            float s = acc[i][j] + bv;
            if (MODE == 1) s = fmaxf(s, 0.f);
            else if (MODE == 2) {
                s = e1[(long)nimg*sC + (long)m*N + n] * (1.f/(1.f + expf(-s)));
            } else if (MODE == 3) {
                int y = n / 20, x = n % 20;
                s += e1[nimg*245 + m] + e2[((long)nimg*245 + m)*100 + (y/2)*10 + (x/2)];
            }
            if (MODE == 4) {
                s = fmaxf(s, 0.f);
                Cp[(long)n*M + m] = s;
            } else {
                Cp[(long)m*N + n] = s;
            }
        }
    }
}

// ---- split-K reduction: out = relu(bias + sum_s partial) ----
__global__ void reduce_relu_kernel(const float* __restrict__ partial, const float* __restrict__ bias,
                                   float* __restrict__ out, int S, int M, int N, long sC) {
    int t = blockIdx.x*blockDim.x + threadIdx.x;
    int total = NI*M*N;
    if (t >= total) return;
    int nimg = t / (M*N);
    int mn   = t % (M*N);
    int m    = mn / N;
    float s = bias[m];
    for (int si = 0; si < S; si++)
        s += partial[((long)si*NI + nimg)*M*N + mn];
    out[(long)nimg*sC + mn] = fmaxf(s, 0.f);
}

// =================== 3x3 stride-2 maxpool SAME ===================
__global__ void maxpool3s2(const float* __restrict__ in, float* __restrict__ out,
                           int C, int Hin, int Hout) {
    int t = blockIdx.x*blockDim.x + threadIdx.x;
    int total = NI*C*Hout*Hout;
    if (t >= total) return;
    int ox = t % Hout;
    int oy = (t / Hout) % Hout;
    int nc = t / (Hout*Hout);
    const float* ip = in + (size_t)nc*Hin*Hin;
    float m = -INFINITY;
    #pragma unroll
    for (int ky = 0; ky < 3; ky++) {
        int iy = 2*oy + ky;
        if (iy >= Hin) continue;
        #pragma unroll
        for (int kx = 0; kx < 3; kx++) {
            int ix = 2*ox + kx;
            if (ix >= Hin) continue;
            m = fmaxf(m, ip[iy*Hin+ix]);
        }
    }
    out[t] = m;
}

__global__ void gap_kernel(const float* __restrict__ c5, float* __restrict__ glb) {
    int t = blockIdx.x*blockDim.x + threadIdx.x;
    if (t >= NI*528) return;
    const float* p = c5 + (size_t)t*100;
    float s = 0.f;
    for (int i = 0; i < 100; i++) s += p[i];
    glb[t] = s / 100.f;
}

__global__ void gfc_kernel(const float* __restrict__ glb, const float* __restrict__ wg,
                           const float* __restrict__ bg, float* __restrict__ gfc) {
    int t = blockIdx.x*blockDim.x + threadIdx.x;
    if (t >= NI*245) return;
    int k = t % 245, n = t / 245;
    float s = bg[k];
    const float* g = glb + n*528;
    for (int c = 0; c < 528; c++) s += g[c] * wg[c*245 + k];
    gfc[t] = s;
}

// ---- depthwise 5x5 SAME + relu ----
__global__ void dw5_kernel(const float* __restrict__ in, const float* __restrict__ w,
                           const float* __restrict__ bias, float* __restrict__ out) {
    int t = blockIdx.x*blockDim.x + threadIdx.x;
    int total = NI*245*400;
    if (t >= total) return;
    int p = t % 400;
    int k = (t / 400) % 245;
    int y = p / 20, x = p % 20;
    const float* ip = in + (size_t)(t/400)*400;
    const float* wk = w + k*25;
    float s = bias[k];
    #pragma unroll
    for (int ky = 0; ky < 5; ky++) {
        int iy = y - 2 + ky;
        if (iy < 0 || iy >= 20) continue;
        #pragma unroll
        for (int kx = 0; kx < 5; kx++) {
            int ix = x - 2 + kx;
            if (ix < 0 || ix >= 20) continue;
            s += ip[iy*20+ix] * wk[ky*5+kx];
        }
    }
    out[t] = fmaxf(s, 0.f);
}

// ---- scores + decoded boxes + sort keys ----
__global__ void scorebox_kernel(const float* __restrict__ clsmap, const float* __restrict__ regmap,
                                float* __restrict__ boxes, unsigned long long* __restrict__ keys) {
    int t = blockIdx.x*blockDim.x + threadIdx.x;
    if (t >= NI*NANCH) return;
    int i = t % NANCH;
    int n = t / NANCH;
    int a = i % 25;
    int x = (i / 25) % 20;
    int y = i / 500;
    int p = y*20 + x;
    const float* cm = clsmap + (size_t)n*50*400;
    float c0 = cm[(a*2  )*400 + p];
    float c1 = cm[(a*2+1)*400 + p];
    float score = 1.f / (1.f + expf(c0 - c1));
    const float* rm = regmap + (size_t)n*100*400;
    float d0 = rm[(a*4  )*400 + p];
    float d1 = rm[(a*4+1)*400 + p];
    float d2 = rm[(a*4+2)*400 + p];
    float d3 = rm[(a*4+3)*400 + p];
    const float scales[5] = {32.f, 64.f, 128.f, 256.f, 512.f};
    const float ratios[5] = {0.5f, 0.75f, 1.0f, 4.0f/3.0f, 2.0f};
    int si = a / 5, ri = a % 5;
    float sq = sqrtf(ratios[ri]);
    float aw = scales[si] / sq;
    float ah = scales[si] * sq;
    float acx = (x + 0.5f) * 16.f;
    float acy = (y + 0.5f) * 16.f;
    float cx = d0*aw + acx;
    float cy = d1*ah + acy;
    float w  = expf(d2) * aw;
    float h  = expf(d3) * ah;
    float* b = boxes + ((size_t)n*NANCH + i)*4;
    b[0] = fminf(fmaxf(cx - 0.5f*w, 0.f), 319.f);
    b[1] = fminf(fmaxf(cy - 0.5f*h, 0.f), 319.f);
    b[2] = fminf(fmaxf(cx + 0.5f*w, 0.f), 319.f);
    b[3] = fminf(fmaxf(cy + 0.5f*h, 0.f), 319.f);
    unsigned sb = __float_as_uint(score);  // score > 0 -> bit-monotone
    keys[t] = ((unsigned long long)sb << 32) | (unsigned long long)(0xFFFFFFFFu - (unsigned)i);
}

// ---- exact top-1000 per image: 64-bit radix select + bitonic sort of 1024 ----
__global__ void __launch_bounds__(1024)
topk_kernel(const unsigned long long* __restrict__ keys,
            const float* __restrict__ boxes, float* __restrict__ bk) {
    __shared__ unsigned int hist[256];
    __shared__ unsigned long long sh_prefix;
    __shared__ int sh_need;
    __shared__ unsigned int sh_cnt;
    __shared__ unsigned long long sk[1024];
    int n = blockIdx.x;
    int tid = threadIdx.x;
    const unsigned long long* kp = keys + (size_t)n*NANCH;

    if (tid == 0) { sh_prefix = 0ull; sh_need = PRENMS; sh_cnt = 0u; }
    __syncthreads();

    // 8-round radix select (MSD first) -> exact 1000th-largest key
    for (int shift = 56; shift >= 0; shift -= 8) {
        if (tid < 256) hist[tid] = 0u;
        __syncthreads();
        unsigned long long prefmask = (shift == 56) ? 0ull : (~0ull << (shift + 8));
        unsigned long long pref = sh_prefix;
        for (int i = tid; i < NANCH; i += 1024) {
            unsigned long long k = kp[i];
            if ((k & prefmask) == pref)
                atomicAdd(&hist[(unsigned)(k >> shift) & 255u], 1u);
        }
        __syncthreads();
        if (tid == 0) {
            int need = sh_need;
            unsigned cum = 0;
            int d = 255;
            for (; d >= 0; d--) { cum += hist[d]; if ((int)cum >= need) break; }
            sh_need = need - (int)(cum - hist[d]);
            sh_prefix = pref | ((unsigned long long)d << shift);
        }
        __syncthreads();
    }
    unsigned long long T = sh_prefix;

    // compact keys >= T (exactly 1000, keys unique), pad to 1024 with 0
    if (tid < 24) sk[1000 + tid] = 0ull;
    for (int i = tid; i < NANCH; i += 1024) {
        unsigned long long k = kp[i];
        if (k >= T) sk[atomicAdd(&sh_cnt, 1u)] = k;
    }
    __syncthreads();

    // bitonic sort 1024 descending
    for (int size = 2; size <= 1024; size <<= 1) {
        for (int stride = size >> 1; stride > 0; stride >>= 1) {
            if (tid < 512) {
                int lo = ((tid & ~(stride-1)) << 1) | (tid & (stride-1));
                int hi = lo + stride;
                unsigned long long a = sk[lo], c = sk[hi];
                bool desc = ((lo & size) == 0);
                if (desc ? (a < c) : (a > c)) { sk[lo] = c; sk[hi] = a; }
            }
            __syncthreads();
        }
    }

    // gather top-1000 boxes
    if (tid < PRENMS) {
        unsigned idx = 0xFFFFFFFFu - (unsigned)(sk[tid] & 0xFFFFFFFFull);
        const float* src = boxes + ((size_t)n*NANCH + idx)*4;
        float* dst = bk + ((size_t)n*PRENMS + tid)*4;
        dst[0] = src[0]; dst[1] = src[1]; dst[2] = src[2]; dst[3] = src[3];
    }
}

// ---- suppression bitmask: mask[n][i][w] bit b = (j=w*32+b > i) && IoU>0.7 ----
__global__ void __launch_bounds__(256)
nms_mask_kernel(const float* __restrict__ bk, unsigned int* __restrict__ mask) {
    __shared__ float4 box[PRENMS];
    __shared__ float  area[PRENMS];
    int n = blockIdx.x;
    int i0 = blockIdx.y * 8;
    int tid = threadIdx.x;
    const float* b = bk + (size_t)n*PRENMS*4;
    for (int i = tid; i < PRENMS; i += 256) {
        float x1 = b[i*4], y1 = b[i*4+1], x2 = b[i*4+2], y2 = b[i*4+3];
        box[i] = make_float4(x1, y1, x2, y2);
        area[i] = (x2-x1)*(y2-y1);
    }
    __syncthreads();
    int w  = tid & 31;
    int il = tid >> 5;
    int i = i0 + il;
    if (i >= PRENMS) return;
    float4 bi = box[i];
    float ai = area[i];
    unsigned m = 0u;
    int jbase = w * 32;
    #pragma unroll 4
    for (int bbit = 0; bbit < 32; bbit++) {
        int j = jbase + bbit;
        if (j > i && j < PRENMS) {
            float ix1 = fmaxf(bi.x, box[j].x);
            float iy1 = fmaxf(bi.y, box[j].y);
            float ix2 = fminf(bi.z, box[j].z);
            float iy2 = fminf(bi.w, box[j].w);
            float inter = fmaxf(ix2-ix1, 0.f) * fmaxf(iy2-iy1, 0.f);
            float iou = inter / (ai + area[j] - inter + 1e-9f);
            if (iou > 0.7f) m |= (1u << bbit);
        }
    }
    mask[((size_t)n*1024 + i)*32 + w] = m;
}

// ---- single-warp NMS scan + stable partition -> 200 rois ----
__global__ void __launch_bounds__(32)
nms_scan_kernel(const unsigned int* __restrict__ mask, const float* __restrict__ bk,
                float* __restrict__ rois, float* __restrict__ out_rois) {
    __shared__ unsigned char keep[PRENMS];
    __shared__ int order[NROIS];
    int n = blockIdx.x;
    int lane = threadIdx.x;
    const unsigned int* mp = mask + (size_t)n*1024*32;
    unsigned removed = 0u;   // lane owns j-bits [lane*32, lane*32+32)
    unsigned next_m = mp[0*32 + lane];
    for (int i = 0; i < PRENMS; i++) {
        unsigned m = next_m;
        if (i + 1 < PRENMS) next_m = mp[(i+1)*32 + lane];
        unsigned rw = __shfl_sync(0xFFFFFFFFu, removed, i >> 5);
        bool keep_i = ((rw >> (i & 31)) & 1u) == 0u;
        if (keep_i) removed |= m;
        if (lane == 0) keep[i] = keep_i ? 1 : 0;
    }
    __syncwarp();
    if (lane == 0) {
        int c = 0;
        for (int i = 0; i < PRENMS && c < NROIS; i++) if (keep[i])  order[c++] = i;
        for (int i = 0; i < PRENMS && c < NROIS; i++) if (!keep[i]) order[c++] = i;
    }
    __syncwarp();
    const float* b = bk + (size_t)n*PRENMS*4;
    for (int r = lane; r < NROIS; r += 32) {
        int idx = order[r];
        float x1 = b[idx*4], y1 = b[idx*4+1], x2 = b[idx*4+2], y2 = b[idx*4+3];
        float* dst = rois + ((size_t)n*NROIS + r)*4;
        dst[0] = x1; dst[1] = y1; dst[2] = x2; dst[3] = y2;
        float* o = out_rois + ((size_t)n*NROIS + r)*4;
        o[0] = x1; o[1] = y1; o[2] = x2; o[3] = y2;
    }
}

// ---- PSRoI pooling: stores TRANSPOSED froiT[c][n*200+r] for fc1 GEMM ----
__global__ void psroi_kernel(const float* __restrict__ fsam, const float* __restrict__ rois,
                             float* __restrict__ froiT) {
    int t = blockIdx.x*blockDim.x + threadIdx.x;
    int total = NI*NROIS*245;
    if (t >= total) return;
    int c = t % 245;
    int r = (t / 245) % NROIS;
    int n = t / (245*NROIS);
    const float* ro = rois + ((size_t)n*NROIS + r)*4;
    float x1 = ro[0] * (1.f/16.f), y1 = ro[1] * (1.f/16.f);
    float x2 = ro[2] * (1.f/16.f), y2 = ro[3] * (1.f/16.f);
    float bw = fmaxf(x2-x1, 0.1f) * (1.f/7.f);
    float bh = fmaxf(y2-y1, 0.1f) * (1.f/7.f);
    int ij = c % 49;
    int i = ij / 7, j = ij % 7;
    float sx = x1 + (j + 0.5f) * bw;
    float sy = y1 + (i + 0.5f) * bh;
    float x = fminf(fmaxf(sx, 0.f), 19.f);
    float y = fminf(fmaxf(sy, 0.f), 19.f);
    int y0 = min(max((int)floorf(y), 0), 18);
    int x0 = min(max((int)floorf(x), 0), 18);
    float wy = y - (float)y0;
    float wx = x - (float)x0;
    const float* f = fsam + ((size_t)n*245 + c)*400;
    float v00 = f[y0*20 + x0],     v01 = f[y0*20 + x0 + 1];
    float v10 = f[(y0+1)*20 + x0], v11 = f[(y0+1)*20 + x0 + 1];
    float v = v00*(1.f-wy)*(1.f-wx) + v01*(1.f-wy)*wx + v10*wy*(1.f-wx) + v11*wy*wx;
    froiT[(size_t)c*(NI*NROIS) + (size_t)n*NROIS + r] = v;
}

// ---- FC2 heads: one warp per (row, output) ----
__global__ void __launch_bounds__(256)
fc2_warp(const float* __restrict__ h, const float* __restrict__ cfw,
         const float* __restrict__ cfb, const float* __restrict__ rfw,
         const float* __restrict__ rfb, float* __restrict__ out_cls,
         float* __restrict__ out_reg) {
    int w = (blockIdx.x*blockDim.x + threadIdx.x) >> 5;
    int lane = threadIdx.x & 31;
    if (w >= NI*NROIS*25) return;
    int m = w % 25;
    int row = w / 25;
    const float* hr = h + (size_t)row*1024;
    float s = 0.f;
    if (m < 21) {
        for (int k = lane; k < 1024; k += 32) s = fmaf(hr[k], cfw[k*21 + m], s);
    } else {
        int mm = m - 21;
        for (int k = lane; k < 1024; k += 32) s = fmaf(hr[k], rfw[k*4 + mm], s);
    }
    #pragma unroll
    for (int o = 16; o > 0; o >>= 1) s += __shfl_down_sync(0xFFFFFFFFu, s, o);
    if (lane == 0) {
        if (m < 21) out_cls[row*21 + m] = s + cfb[m];
        else        out_reg[row*4 + (m-21)] = s + rfb[m-21];
    }
}

extern "C" void kernel_launch(void* const* d_in, const int* in_sizes, int n_in,
                              void* d_out, int out_size) {
    const float* x      = (const float*)d_in[0];
    const float* w1     = (const float*)d_in[1];
    const float* b1     = (const float*)d_in[2];
    const float* w2     = (const float*)d_in[3];
    const float* b2     = (const float*)d_in[4];
    const float* w3     = (const float*)d_in[5];
    const float* b3     = (const float*)d_in[6];
    const float* w4     = (const float*)d_in[7];
    const float* b4     = (const float*)d_in[8];
    const float* cem_w4 = (const float*)d_in[9];
    const float* cem_b4 = (const float*)d_in[10];
    const float* cem_w5 = (const float*)d_in[11];
    const float* cem_b5 = (const float*)d_in[12];
    const float* cem_wg = (const float*)d_in[13];
    const float* cem_bg = (const float*)d_in[14];
    const float* rpn_dw = (const float*)d_in[15];
    const float* rpn_dwb= (const float*)d_in[16];
    const float* rpn_pw = (const float*)d_in[17];
    const float* rpn_pwb= (const float*)d_in[18];
    const float* cls_w  = (const float*)d_in[19];
    const float* cls_b  = (const float*)d_in[20];
    const float* reg_w  = (const float*)d_in[21];
    const float* reg_b  = (const float*)d_in[22];
    const float* sam_w  = (const float*)d_in[23];
    const float* sam_b  = (const float*)d_in[24];
    const float* fc_w   = (const float*)d_in[25];
    const float* fc_b   = (const float*)d_in[26];
    const float* cls_fw = (const float*)d_in[27];
    const float* cls_fb = (const float*)d_in[28];
    const float* reg_fw = (const float*)d_in[29];
    const float* reg_fb = (const float*)d_in[30];
    float* out = (float*)d_out;

    float* buf = nullptr;
    cudaGetSymbolAddress((void**)&buf, g_buf);
    unsigned long long* keys = nullptr;
    cudaGetSymbolAddress((void**)&keys, g_keys);
    unsigned int* mask = nullptr;
    cudaGetSymbolAddress((void**)&mask, g_mask);

    const int TB = 256;
    float* part = buf + O_PART;

    // ---- conv1: 3->24, 320->160 (implicit GEMM) ----
    gemm_tiled<1,false,true><<<dim3(CDIV(25600,64), 1, NI), 256>>>(
        w1, x, b1, buf+O_C1, 24, 27, 25600, (long)3*320*320, (long)24*25600,
        nullptr, nullptr, 3, 320, 160, 1, 27);
    maxpool3s2<<<CDIV(NI*24*80*80, TB), TB>>>(buf+O_C1, buf+O_P1, 24, 160, 80);
    // ---- conv2: 24->132, 80->40 (implicit GEMM) ----
    gemm_tiled<1,false,true><<<dim3(CDIV(1600,64), CDIV(132,64), NI), 256>>>(
        w2, buf+O_P1, b2, buf+O_C3, 132, 216, 1600, (long)24*80*80, (long)132*1600,
        nullptr, nullptr, 24, 80, 40, 1, 216);
    // ---- conv3: 132->264, 40->20 (implicit GEMM, split-K=4) ----
    gemm_tiled<5,false,true><<<dim3(CDIV(400,64), CDIV(264,64), NI*4), 256>>>(
        w3, buf+O_C3, nullptr, part, 264, 1188, 400, (long)132*40*40, 0,
        nullptr, nullptr, 132, 40, 20, 4, 297);
    reduce_relu_kernel<<<CDIV(NI*264*400, TB), TB>>>(part, b3, buf+O_C4, 4, 264, 400, (long)264*400);
    // ---- conv4: 264->528, 20->10 (implicit GEMM, split-K=4) ----
    gemm_tiled<5,false,true><<<dim3(CDIV(100,64), CDIV(528,64), NI*4), 256>>>(
        w4, buf+O_C4, nullptr, part, 528, 2376, 100, (long)264*20*20, 0,
        nullptr, nullptr, 264, 20, 10, 4, 594);
    reduce_relu_kernel<<<CDIV(NI*528*100, TB), TB>>>(part, b4, buf+O_C5, 4, 528, 100, (long)528*100);

    // ---- CEM ----
    gap_kernel<<<CDIV(NI*528, TB), TB>>>(buf+O_C5, buf+O_GLB);
    gfc_kernel<<<CDIV(NI*245, TB), TB>>>(buf+O_GLB, cem_wg, cem_bg, buf+O_GFC);
    gemm_tiled<0,false,false><<<dim3(CDIV(100,64), CDIV(245,64), NI), 256>>>(
        cem_w5, buf+O_C5, cem_b5, buf+O_CEM5, 245, 528, 100,
        (long)528*100, (long)245*100, nullptr, nullptr, 0, 0, 0, 1, 528);
    gemm_tiled<3,false,false><<<dim3(CDIV(400,64), CDIV(245,64), NI), 256>>>(
        cem_w4, buf+O_C4, cem_b4, buf+O_FCEM, 245, 264, 400,
        (long)264*400, (long)245*400, buf+O_GFC, buf+O_CEM5, 0, 0, 0, 1, 264);

    // ---- RPN ----
    dw5_kernel<<<CDIV(NI*245*400, TB), TB>>>(buf+O_FCEM, rpn_dw, rpn_dwb, buf+O_T);
    gemm_tiled<1,false,false><<<dim3(CDIV(400,64), CDIV(256,64), NI), 256>>>(
        rpn_pw, buf+O_T, rpn_pwb, buf+O_FRPN, 256, 245, 400,
        (long)245*400, (long)256*400, nullptr, nullptr, 0, 0, 0, 1, 245);
    gemm_tiled<0,false,false><<<dim3(CDIV(400,64), CDIV(50,64), NI), 256>>>(
        cls_w, buf+O_FRPN, cls_b, buf+O_CLS, 50, 256, 400,
        (long)256*400, (long)50*400, nullptr, nullptr, 0, 0, 0, 1, 256);
    gemm_tiled<0,false,false><<<dim3(CDIV(400,64), CDIV(100,64), NI), 256>>>(
        reg_w, buf+O_FRPN, reg_b, buf+O_REG, 100, 256, 400,
        (long)256*400, (long)100*400, nullptr, nullptr, 0, 0, 0, 1, 256);
    gemm_tiled<2,false,false><<<dim3(CDIV(400,64), CDIV(245,64), NI), 256>>>(
        sam_w, buf+O_FRPN, sam_b, buf+O_FSAM, 245, 256, 400,
        (long)256*400, (long)245*400, buf+O_FCEM, nullptr, 0, 0, 0, 1, 256);

    // ---- proposals ----
    scorebox_kernel<<<CDIV(NI*NANCH, TB), TB>>>(buf+O_CLS, buf+O_REG, buf+O_BOX, keys);
    topk_kernel<<<NI, 1024>>>(keys, buf+O_BOX, buf+O_BK);
    nms_mask_kernel<<<dim3(NI, 125), 256>>>(buf+O_BK, mask);
    nms_scan_kernel<<<NI, 32>>>(mask, buf+O_BK, buf+O_ROI,
                                out + (size_t)NI*NROIS*21 + (size_t)NI*NROIS*4);

    // ---- head ----
    psroi_kernel<<<CDIV(NI*NROIS*245, TB), TB>>>(buf+O_FSAM, buf+O_ROI, buf+O_FROI);
    gemm_tiled<4,true,false><<<dim3(CDIV(NI*NROIS,64), CDIV(1024,64), 1), 256>>>(
        fc_w, buf+O_FROI, fc_b, buf+O_H, 1024, 245, NI*NROIS, 0, 0,
        nullptr, nullptr, 0, 0, 0, 1, 245);
    fc2_warp<<<CDIV(NI*NROIS*25*32, TB), TB>>>(buf+O_H, cls_fw, cls_fb, reg_fw, reg_fb,
                                               out, out + (size_t)NI*NROIS*21);
}